// round 1
// baseline (speedup 1.0000x reference)
#include <cuda_runtime.h>
#include <math.h>
#include <stdint.h>

// Problem constants (fixed by the dataset)
#define S 2048
#define H 1024
#define F 4096
#define E 8
#define CAP 512   // ceil(S*TOPK*CAP_FACTOR/E) = ceil(2048*2/8) = 512

// ---------------- device scratch (no runtime allocation allowed) ----------------
__device__ float g_gates[S * E];
__device__ int   g_idx1[S];
__device__ int   g_idx2[S];
__device__ int   g_c1[S];
__device__ int   g_c2[S];
__device__ float g_w1s[S];
__device__ float g_w2s[S];
__device__ int   g_slot_tok[E * CAP];
__device__ float g_h[(size_t)E * CAP * F];    // 64 MB: gelu(dispatched @ w1)
__device__ float g_eo[(size_t)E * CAP * H];   // 16 MB: expert outputs

// ---------------- init: empty slots -> -1 ----------------
__global__ void init_kernel() {
    int i = blockIdx.x * blockDim.x + threadIdx.x;
    if (i < E * CAP) g_slot_tok[i] = -1;
}

// ---------------- gating: logits, softmax, top-2 ----------------
__global__ void gate_kernel(const float* __restrict__ x, const float* __restrict__ wg) {
    int warp = (blockIdx.x * blockDim.x + threadIdx.x) >> 5;
    int lane = threadIdx.x & 31;
    if (warp >= S) return;
    const float* xr = x + (size_t)warp * H;

    float acc[E];
#pragma unroll
    for (int e = 0; e < E; e++) acc[e] = 0.0f;

    for (int k = lane; k < H; k += 32) {
        float xv = xr[k];
        const float* wr = wg + (size_t)k * E;
#pragma unroll
        for (int e = 0; e < E; e++) acc[e] += xv * wr[e];
    }
#pragma unroll
    for (int off = 16; off > 0; off >>= 1) {
#pragma unroll
        for (int e = 0; e < E; e++)
            acc[e] += __shfl_down_sync(0xffffffffu, acc[e], off);
    }
    if (lane == 0) {
        // softmax over E=8
        float mx = acc[0];
#pragma unroll
        for (int e = 1; e < E; e++) mx = fmaxf(mx, acc[e]);
        float g[E], sum = 0.0f;
#pragma unroll
        for (int e = 0; e < E; e++) { g[e] = expf(acc[e] - mx); sum += g[e]; }
        float inv = 1.0f / sum;

        // argmax of logits (== argmax of gates), first-index tie-break
        int i1 = 0; float v1 = acc[0];
#pragma unroll
        for (int e = 1; e < E; e++) if (acc[e] > v1) { v1 = acc[e]; i1 = e; }
        int i2 = -1; float v2 = -3.4e38f;
#pragma unroll
        for (int e = 0; e < E; e++)
            if (e != i1 && acc[e] > v2) { v2 = acc[e]; i2 = e; }

#pragma unroll
        for (int e = 0; e < E; e++) g_gates[warp * E + e] = g[e] * inv;
        g_idx1[warp] = i1;
        g_idx2[warp] = i2;
    }
}

// ---------------- scan: cumsum ranks, capacity drop, combine weights, aux ----------------
// One block, 8 warps (one per expert).
__global__ void scan_kernel(float* __restrict__ out) {
    __shared__ int   sh_count1[E];
    __shared__ float sh_me[E];
    int warp = threadIdx.x >> 5;
    int lane = threadIdx.x & 31;
    unsigned lt_mask = (lane == 0) ? 0u : (0xffffffffu >> (32 - lane));

    // Phase A: first-choice ranks (loc1) + pre-drop counts + gate sums (me)
    {
        int e = warp;
        int rank = 0;
        float mesum = 0.0f;
        for (int t0 = 0; t0 < S; t0 += 32) {
            int s = t0 + lane;
            int bit = (g_idx1[s] == e);
            unsigned m = __ballot_sync(0xffffffffu, bit);
            if (bit) {
                int r = rank + __popc(m & lt_mask);
                if (r < CAP) { g_c1[s] = r; g_slot_tok[e * CAP + r] = s; }
                else         { g_c1[s] = -1; }
            }
            rank += __popc(m);
            mesum += g_gates[s * E + e];
        }
#pragma unroll
        for (int off = 16; off > 0; off >>= 1)
            mesum += __shfl_down_sync(0xffffffffu, mesum, off);
        if (lane == 0) { sh_count1[e] = rank; sh_me[e] = mesum; }
    }
    __syncthreads();

    // Phase B: second-choice ranks, offset by total count1 (DeepSpeed top2gating)
    {
        int e = warp;
        int base = sh_count1[e];
        int rank = 0;
        for (int t0 = 0; t0 < S; t0 += 32) {
            int s = t0 + lane;
            int bit = (g_idx2[s] == e);
            unsigned m = __ballot_sync(0xffffffffu, bit);
            if (bit) {
                int r = base + rank + __popc(m & lt_mask);
                if (r < CAP) { g_c2[s] = r; g_slot_tok[e * CAP + r] = s; }
                else         { g_c2[s] = -1; }
            }
            rank += __popc(m);
        }
    }
    __syncthreads();

    // Phase C: normalized combine weights (post-drop)
    for (int s = threadIdx.x; s < S; s += blockDim.x) {
        int i1 = g_idx1[s], i2 = g_idx2[s];
        float g1 = (g_c1[s] >= 0) ? g_gates[s * E + i1] : 0.0f;
        float g2 = (g_c2[s] >= 0) ? g_gates[s * E + i2] : 0.0f;
        float denom = fmaxf(g1 + g2, 1.1920929e-7f);
        g_w1s[s] = g1 / denom;
        g_w2s[s] = g2 / denom;
    }

    // Phase D: l_aux + exp_counts tail
    if (threadIdx.x == 0) {
        float laux = 0.0f;
        const float invS = 1.0f / (float)S;
#pragma unroll
        for (int e = 0; e < E; e++)
            laux += (sh_me[e] * invS) * ((float)sh_count1[e] * invS);
        laux = laux * (float)E * 0.01f;   // mean_e(me*ce)*E*E*0.01
        out[(size_t)S * H] = laux;
#pragma unroll
        for (int e = 0; e < E; e++)
            out[(size_t)S * H + 1 + e] = (float)sh_count1[e];
    }
}

// ---------------- GEMM: 128x128x8 tile, 256 threads, 8x8 microtile ----------------
__device__ __forceinline__ float gelu_tanh(float v) {
    const float c = 0.7978845608028654f;
    float t = tanhf(c * (v + 0.044715f * v * v * v));
    return 0.5f * v * (1.0f + t);
}

template <bool GATHER, bool GELU>
__global__ void __launch_bounds__(256)
sgemm_kernel(const float* __restrict__ A, const float* __restrict__ B,
             float* __restrict__ Cmat, int K, int N,
             size_t strideA_e, size_t strideB_e, size_t strideC_e) {
    int e = blockIdx.z;
    const float* Ae = GATHER ? A : (A + e * strideA_e);
    const float* Be = B + e * strideB_e;
    float* Ce = Cmat + e * strideC_e;

    __shared__ float As[8][128];
    __shared__ float Bs[8][128];

    int tid = threadIdx.x;
    int m0 = blockIdx.y * 128;
    int n0 = blockIdx.x * 128;

    int arow = tid >> 1;           // 0..127
    int acol = (tid & 1) * 4;      // 0 or 4
    int brow = tid >> 5;           // 0..7
    int bcol = (tid & 31) * 4;     // 0..124

    const float* Aptr;
    if (GATHER) {
        int tok = g_slot_tok[e * CAP + m0 + arow];
        Aptr = (tok >= 0) ? (Ae + (size_t)tok * K) : nullptr;
    } else {
        Aptr = Ae + (size_t)(m0 + arow) * K;
    }
    const float* Bptr = Be + (size_t)brow * N + n0 + bcol;

    int tx = tid & 15;
    int ty = tid >> 4;

    float acc[8][8];
#pragma unroll
    for (int i = 0; i < 8; i++)
#pragma unroll
        for (int j = 0; j < 8; j++) acc[i][j] = 0.0f;

    for (int k0 = 0; k0 < K; k0 += 8) {
        float4 av = make_float4(0.f, 0.f, 0.f, 0.f);
        if (!GATHER || Aptr)
            av = *reinterpret_cast<const float4*>(Aptr + k0 + acol);
        float4 bv = *reinterpret_cast<const float4*>(Bptr + (size_t)k0 * N);

        As[acol + 0][arow] = av.x;
        As[acol + 1][arow] = av.y;
        As[acol + 2][arow] = av.z;
        As[acol + 3][arow] = av.w;
        *reinterpret_cast<float4*>(&Bs[brow][bcol]) = bv;
        __syncthreads();

#pragma unroll
        for (int kk = 0; kk < 8; kk++) {
            float4 a0 = *reinterpret_cast<const float4*>(&As[kk][ty * 4]);
            float4 a1 = *reinterpret_cast<const float4*>(&As[kk][64 + ty * 4]);
            float4 b0 = *reinterpret_cast<const float4*>(&Bs[kk][tx * 4]);
            float4 b1 = *reinterpret_cast<const float4*>(&Bs[kk][64 + tx * 4]);
            float a[8] = {a0.x, a0.y, a0.z, a0.w, a1.x, a1.y, a1.z, a1.w};
            float b[8] = {b0.x, b0.y, b0.z, b0.w, b1.x, b1.y, b1.z, b1.w};
#pragma unroll
            for (int i = 0; i < 8; i++)
#pragma unroll
                for (int j = 0; j < 8; j++)
                    acc[i][j] = fmaf(a[i], b[j], acc[i][j]);
        }
        __syncthreads();
    }

#pragma unroll
    for (int i = 0; i < 8; i++) {
        int row = m0 + ((i < 4) ? (ty * 4 + i) : (64 + ty * 4 + (i - 4)));
        float* crow = Ce + (size_t)row * N + n0;
#pragma unroll
        for (int jh = 0; jh < 2; jh++) {
            int jb = jh * 4;
            float4 v = make_float4(acc[i][jb], acc[i][jb + 1], acc[i][jb + 2], acc[i][jb + 3]);
            if (GELU) {
                v.x = gelu_tanh(v.x); v.y = gelu_tanh(v.y);
                v.z = gelu_tanh(v.z); v.w = gelu_tanh(v.w);
            }
            int col = (jh == 0) ? (tx * 4) : (64 + tx * 4);
            *reinterpret_cast<float4*>(crow + col) = v;
        }
    }
}

// ---------------- combine: output[s] = w1*eo[e1,c1] + w2*eo[e2,c2] ----------------
__global__ void combine_kernel(float* __restrict__ out) {
    int s = blockIdx.x;
    int c1 = g_c1[s], c2 = g_c2[s];
    float w1 = g_w1s[s], w2 = g_w2s[s];
    const float* r1 = (c1 >= 0) ? (g_eo + ((size_t)g_idx1[s] * CAP + c1) * H) : nullptr;
    const float* r2 = (c2 >= 0) ? (g_eo + ((size_t)g_idx2[s] * CAP + c2) * H) : nullptr;

    int hh = threadIdx.x * 4;  // 256 threads * 4 = 1024 = H
    float4 v = make_float4(0.f, 0.f, 0.f, 0.f);
    if (r1) {
        float4 a = *reinterpret_cast<const float4*>(r1 + hh);
        v.x += w1 * a.x; v.y += w1 * a.y; v.z += w1 * a.z; v.w += w1 * a.w;
    }
    if (r2) {
        float4 a = *reinterpret_cast<const float4*>(r2 + hh);
        v.x += w2 * a.x; v.y += w2 * a.y; v.z += w2 * a.z; v.w += w2 * a.w;
    }
    *reinterpret_cast<float4*>(out + (size_t)s * H + hh) = v;
}

// ---------------- launch ----------------
extern "C" void kernel_launch(void* const* d_in, const int* in_sizes, int n_in,
                              void* d_out, int out_size) {
    const float* x  = (const float*)d_in[0];  // [S, H]
    const float* wg = (const float*)d_in[1];  // [H, E]
    const float* w1 = (const float*)d_in[2];  // [E, H, F]
    const float* w2 = (const float*)d_in[3];  // [E, F, H]
    float* out = (float*)d_out;               // [S*H] ++ [l_aux] ++ [E counts]

    float* hbuf = nullptr;
    float* eobuf = nullptr;
    cudaGetSymbolAddress((void**)&hbuf, g_h);
    cudaGetSymbolAddress((void**)&eobuf, g_eo);

    init_kernel<<<(E * CAP + 255) / 256, 256>>>();
    gate_kernel<<<(S * 32 + 255) / 256, 256>>>(x, wg);
    scan_kernel<<<1, 256>>>(out);

    // GEMM1: gathered x [CAP,H] @ w1[e] [H,F] -> gelu -> g_h [CAP,F]
    sgemm_kernel<true, true><<<dim3(F / 128, CAP / 128, E), 256>>>(
        x, w1, hbuf, H, F, 0, (size_t)H * F, (size_t)CAP * F);

    // GEMM2: g_h [CAP,F] @ w2[e] [F,H] -> g_eo [CAP,H]
    sgemm_kernel<false, false><<<dim3(H / 128, CAP / 128, E), 256>>>(
        hbuf, w2, eobuf, F, H, (size_t)CAP * F, (size_t)F * H, (size_t)CAP * H);

    combine_kernel<<<S, 256>>>(out);
}

// round 2
// speedup vs baseline: 2.5289x; 2.5289x over previous
#include <cuda_runtime.h>
#include <math.h>
#include <stdint.h>

// Problem constants (fixed by the dataset)
#define S 2048
#define H 1024
#define F 4096
#define E 8
#define CAP 512   // ceil(S*TOPK*CAP_FACTOR/E)

// ---------------- device scratch (no runtime allocation allowed) ----------------
__device__ float g_gates[S * E];
__device__ int   g_idx1[S];
__device__ int   g_idx2[S];
__device__ int   g_c1[S];
__device__ int   g_c2[S];
__device__ float g_w1s[S];
__device__ float g_w2s[S];
__device__ int   g_slot_tok[E * CAP];
__device__ float g_h[(size_t)E * CAP * F];    // 64 MB: gelu(dispatched @ w1)
__device__ float g_eo[(size_t)E * CAP * H];   // 16 MB: expert outputs

// ---------------- init: empty slots -> -1 ----------------
__global__ void init_kernel() {
    int i = blockIdx.x * blockDim.x + threadIdx.x;
    if (i < E * CAP) g_slot_tok[i] = -1;
}

// ---------------- gating: logits, softmax, top-2 ----------------
__global__ void gate_kernel(const float* __restrict__ x, const float* __restrict__ wg) {
    int warp = (blockIdx.x * blockDim.x + threadIdx.x) >> 5;
    int lane = threadIdx.x & 31;
    if (warp >= S) return;
    const float* xr = x + (size_t)warp * H;

    float acc[E];
#pragma unroll
    for (int e = 0; e < E; e++) acc[e] = 0.0f;

    for (int k = lane; k < H; k += 32) {
        float xv = xr[k];
        const float* wr = wg + (size_t)k * E;
#pragma unroll
        for (int e = 0; e < E; e++) acc[e] += xv * wr[e];
    }
#pragma unroll
    for (int off = 16; off > 0; off >>= 1) {
#pragma unroll
        for (int e = 0; e < E; e++)
            acc[e] += __shfl_down_sync(0xffffffffu, acc[e], off);
    }
    if (lane == 0) {
        float mx = acc[0];
#pragma unroll
        for (int e = 1; e < E; e++) mx = fmaxf(mx, acc[e]);
        float g[E], sum = 0.0f;
#pragma unroll
        for (int e = 0; e < E; e++) { g[e] = expf(acc[e] - mx); sum += g[e]; }
        float inv = 1.0f / sum;

        int i1 = 0; float v1 = acc[0];
#pragma unroll
        for (int e = 1; e < E; e++) if (acc[e] > v1) { v1 = acc[e]; i1 = e; }
        int i2 = -1; float v2 = -3.4e38f;
#pragma unroll
        for (int e = 0; e < E; e++)
            if (e != i1 && acc[e] > v2) { v2 = acc[e]; i2 = e; }

#pragma unroll
        for (int e = 0; e < E; e++) g_gates[warp * E + e] = g[e] * inv;
        g_idx1[warp] = i1;
        g_idx2[warp] = i2;
    }
}

// ---------------- scan: ranks, capacity drop, combine weights, aux ----------------
__global__ void scan_kernel(float* __restrict__ out) {
    __shared__ int   sh_count1[E];
    __shared__ float sh_me[E];
    int warp = threadIdx.x >> 5;
    int lane = threadIdx.x & 31;
    unsigned lt_mask = (lane == 0) ? 0u : (0xffffffffu >> (32 - lane));

    {
        int e = warp;
        int rank = 0;
        float mesum = 0.0f;
        for (int t0 = 0; t0 < S; t0 += 32) {
            int s = t0 + lane;
            int bit = (g_idx1[s] == e);
            unsigned m = __ballot_sync(0xffffffffu, bit);
            if (bit) {
                int r = rank + __popc(m & lt_mask);
                if (r < CAP) { g_c1[s] = r; g_slot_tok[e * CAP + r] = s; }
                else         { g_c1[s] = -1; }
            }
            rank += __popc(m);
            mesum += g_gates[s * E + e];
        }
#pragma unroll
        for (int off = 16; off > 0; off >>= 1)
            mesum += __shfl_down_sync(0xffffffffu, mesum, off);
        if (lane == 0) { sh_count1[e] = rank; sh_me[e] = mesum; }
    }
    __syncthreads();

    {
        int e = warp;
        int base = sh_count1[e];
        int rank = 0;
        for (int t0 = 0; t0 < S; t0 += 32) {
            int s = t0 + lane;
            int bit = (g_idx2[s] == e);
            unsigned m = __ballot_sync(0xffffffffu, bit);
            if (bit) {
                int r = base + rank + __popc(m & lt_mask);
                if (r < CAP) { g_c2[s] = r; g_slot_tok[e * CAP + r] = s; }
                else         { g_c2[s] = -1; }
            }
            rank += __popc(m);
        }
    }
    __syncthreads();

    for (int s = threadIdx.x; s < S; s += blockDim.x) {
        int i1 = g_idx1[s], i2 = g_idx2[s];
        float g1 = (g_c1[s] >= 0) ? g_gates[s * E + i1] : 0.0f;
        float g2 = (g_c2[s] >= 0) ? g_gates[s * E + i2] : 0.0f;
        float denom = fmaxf(g1 + g2, 1.1920929e-7f);
        g_w1s[s] = g1 / denom;
        g_w2s[s] = g2 / denom;
    }

    if (threadIdx.x == 0) {
        float laux = 0.0f;
        const float invS = 1.0f / (float)S;
#pragma unroll
        for (int e = 0; e < E; e++)
            laux += (sh_me[e] * invS) * ((float)sh_count1[e] * invS);
        laux = laux * (float)E * 0.01f;
        out[(size_t)S * H] = laux;
#pragma unroll
        for (int e = 0; e < E; e++)
            out[(size_t)S * H + 1 + e] = (float)sh_count1[e];
    }
}

// ---------------- TF32 tensor-core GEMM ----------------
__device__ __forceinline__ float gelu_tanh(float v) {
    const float c = 0.7978845608028654f;
    float t = tanhf(c * (v + 0.044715f * v * v * v));
    return 0.5f * v * (1.0f + t);
}

__device__ __forceinline__ uint32_t f2tf32(float f) {
    uint32_t r;
    asm("cvt.rna.tf32.f32 %0, %1;" : "=r"(r) : "f"(f));
    return r;
}

__device__ __forceinline__ void mma_tf32(float c[4], const uint32_t a[4], const uint32_t b[2]) {
    asm volatile(
        "mma.sync.aligned.m16n8k8.row.col.f32.tf32.tf32.f32 "
        "{%0,%1,%2,%3}, {%4,%5,%6,%7}, {%8,%9}, {%0,%1,%2,%3};\n"
        : "+f"(c[0]), "+f"(c[1]), "+f"(c[2]), "+f"(c[3])
        : "r"(a[0]), "r"(a[1]), "r"(a[2]), "r"(a[3]), "r"(b[0]), "r"(b[1]));
}

// Block tile 128x128, BK=16, 256 threads = 8 warps (2 M x 4 N), warp tile 64x32.
#define BK 16
#define APAD 8   // As row stride 136: conflict-free fragment loads
#define BPAD 8

template <bool GATHER, bool GELU>
__global__ void __launch_bounds__(256)
mma_gemm_kernel(const float* __restrict__ A, const float* __restrict__ B,
                float* __restrict__ Cmat, int K, int N,
                size_t strideA_e, size_t strideB_e, size_t strideC_e) {
    __shared__ uint32_t As[BK][128 + APAD];   // [k][m]
    __shared__ uint32_t Bs[BK][128 + BPAD];   // [k][n]

    int e = blockIdx.z;
    const float* Ae = GATHER ? A : (A + e * strideA_e);
    const float* Be = B + e * strideB_e;
    float* Ce = Cmat + e * strideC_e;

    int tid  = threadIdx.x;
    int m0   = blockIdx.y * 128;
    int n0   = blockIdx.x * 128;

    // ---- global load mapping ----
    // A tile: 128 rows x 16 cols. thread -> rows (tid/4) and (tid/4 + 64), k-offset (tid%4)*4
    int ar  = tid >> 2;            // 0..63
    int ak4 = (tid & 3) * 4;       // 0,4,8,12
    const float* Aptr0;
    const float* Aptr1;
    if (GATHER) {
        int t0 = g_slot_tok[e * CAP + m0 + ar];
        int t1 = g_slot_tok[e * CAP + m0 + ar + 64];
        Aptr0 = (t0 >= 0) ? (Ae + (size_t)t0 * K) : nullptr;
        Aptr1 = (t1 >= 0) ? (Ae + (size_t)t1 * K) : nullptr;
    } else {
        Aptr0 = Ae + (size_t)(m0 + ar) * K;
        Aptr1 = Ae + (size_t)(m0 + ar + 64) * K;
    }
    // B tile: 16 rows x 128 cols. thread -> k rows (tid/32) and (tid/32+8), col (tid%32)*4
    int bk  = tid >> 5;            // 0..7
    int bc  = (tid & 31) * 4;
    const float* Bptr = Be + (size_t)bk * N + n0 + bc;

    // ---- warp/fragment mapping ----
    int w      = tid >> 5;
    int lane   = tid & 31;
    int warp_m = (w & 1) * 64;     // 0 or 64
    int warp_n = (w >> 1) * 32;    // 0,32,64,96
    int group  = lane >> 2;        // 0..7
    int tg     = lane & 3;         // 0..3

    float acc[4][4][4];
#pragma unroll
    for (int i = 0; i < 4; i++)
#pragma unroll
        for (int j = 0; j < 4; j++)
#pragma unroll
            for (int r = 0; r < 4; r++) acc[i][j][r] = 0.0f;

    // prefetch first tile
    float4 pa0 = make_float4(0.f,0.f,0.f,0.f), pa1 = pa0, pb0, pb1;
    if (!GATHER || Aptr0) pa0 = *reinterpret_cast<const float4*>(Aptr0 + ak4);
    if (!GATHER || Aptr1) pa1 = *reinterpret_cast<const float4*>(Aptr1 + ak4);
    pb0 = *reinterpret_cast<const float4*>(Bptr);
    pb1 = *reinterpret_cast<const float4*>(Bptr + (size_t)8 * N);

    for (int k0 = 0; k0 < K; k0 += BK) {
        // store current tile to smem (tf32-rounded)
        As[ak4 + 0][ar]      = f2tf32(pa0.x);
        As[ak4 + 1][ar]      = f2tf32(pa0.y);
        As[ak4 + 2][ar]      = f2tf32(pa0.z);
        As[ak4 + 3][ar]      = f2tf32(pa0.w);
        As[ak4 + 0][ar + 64] = f2tf32(pa1.x);
        As[ak4 + 1][ar + 64] = f2tf32(pa1.y);
        As[ak4 + 2][ar + 64] = f2tf32(pa1.z);
        As[ak4 + 3][ar + 64] = f2tf32(pa1.w);
        Bs[bk][bc + 0]     = f2tf32(pb0.x);
        Bs[bk][bc + 1]     = f2tf32(pb0.y);
        Bs[bk][bc + 2]     = f2tf32(pb0.z);
        Bs[bk][bc + 3]     = f2tf32(pb0.w);
        Bs[bk + 8][bc + 0] = f2tf32(pb1.x);
        Bs[bk + 8][bc + 1] = f2tf32(pb1.y);
        Bs[bk + 8][bc + 2] = f2tf32(pb1.z);
        Bs[bk + 8][bc + 3] = f2tf32(pb1.w);
        __syncthreads();

        // prefetch next tile (overlaps with mma compute below)
        if (k0 + BK < K) {
            int kn = k0 + BK;
            if (!GATHER || Aptr0) pa0 = *reinterpret_cast<const float4*>(Aptr0 + kn + ak4);
            if (!GATHER || Aptr1) pa1 = *reinterpret_cast<const float4*>(Aptr1 + kn + ak4);
            pb0 = *reinterpret_cast<const float4*>(Bptr + (size_t)kn * N);
            pb1 = *reinterpret_cast<const float4*>(Bptr + (size_t)(kn + 8) * N);
        }

        // compute: 2 k-steps of 8
#pragma unroll
        for (int ks = 0; ks < 2; ks++) {
            int kb = ks * 8 + tg;
            uint32_t af[4][4];
#pragma unroll
            for (int i = 0; i < 4; i++) {
                int m = warp_m + i * 16 + group;
                af[i][0] = As[kb][m];
                af[i][1] = As[kb][m + 8];
                af[i][2] = As[kb + 4][m];
                af[i][3] = As[kb + 4][m + 8];
            }
            uint32_t bf[4][2];
#pragma unroll
            for (int j = 0; j < 4; j++) {
                int n = warp_n + j * 8 + group;
                bf[j][0] = Bs[kb][n];
                bf[j][1] = Bs[kb + 4][n];
            }
#pragma unroll
            for (int i = 0; i < 4; i++)
#pragma unroll
                for (int j = 0; j < 4; j++)
                    mma_tf32(acc[i][j], af[i], bf[j]);
        }
        __syncthreads();
    }

    // ---- epilogue ----
#pragma unroll
    for (int i = 0; i < 4; i++) {
        int row0 = m0 + warp_m + i * 16 + group;
#pragma unroll
        for (int j = 0; j < 4; j++) {
            int col = n0 + warp_n + j * 8 + tg * 2;
            float2 v0 = make_float2(acc[i][j][0], acc[i][j][1]);
            float2 v1 = make_float2(acc[i][j][2], acc[i][j][3]);
            if (GELU) {
                v0.x = gelu_tanh(v0.x); v0.y = gelu_tanh(v0.y);
                v1.x = gelu_tanh(v1.x); v1.y = gelu_tanh(v1.y);
            }
            *reinterpret_cast<float2*>(Ce + (size_t)row0 * N + col)       = v0;
            *reinterpret_cast<float2*>(Ce + (size_t)(row0 + 8) * N + col) = v1;
        }
    }
}

// ---------------- combine ----------------
__global__ void combine_kernel(float* __restrict__ out) {
    int s = blockIdx.x;
    int c1 = g_c1[s], c2 = g_c2[s];
    float w1 = g_w1s[s], w2 = g_w2s[s];
    const float* r1 = (c1 >= 0) ? (g_eo + ((size_t)g_idx1[s] * CAP + c1) * H) : nullptr;
    const float* r2 = (c2 >= 0) ? (g_eo + ((size_t)g_idx2[s] * CAP + c2) * H) : nullptr;

    int hh = threadIdx.x * 4;
    float4 v = make_float4(0.f, 0.f, 0.f, 0.f);
    if (r1) {
        float4 a = *reinterpret_cast<const float4*>(r1 + hh);
        v.x += w1 * a.x; v.y += w1 * a.y; v.z += w1 * a.z; v.w += w1 * a.w;
    }
    if (r2) {
        float4 a = *reinterpret_cast<const float4*>(r2 + hh);
        v.x += w2 * a.x; v.y += w2 * a.y; v.z += w2 * a.z; v.w += w2 * a.w;
    }
    *reinterpret_cast<float4*>(out + (size_t)s * H + hh) = v;
}

// ---------------- launch ----------------
extern "C" void kernel_launch(void* const* d_in, const int* in_sizes, int n_in,
                              void* d_out, int out_size) {
    const float* x  = (const float*)d_in[0];  // [S, H]
    const float* wg = (const float*)d_in[1];  // [H, E]
    const float* w1 = (const float*)d_in[2];  // [E, H, F]
    const float* w2 = (const float*)d_in[3];  // [E, F, H]
    float* out = (float*)d_out;

    float* hbuf = nullptr;
    float* eobuf = nullptr;
    cudaGetSymbolAddress((void**)&hbuf, g_h);
    cudaGetSymbolAddress((void**)&eobuf, g_eo);

    init_kernel<<<(E * CAP + 255) / 256, 256>>>();
    gate_kernel<<<(S * 32 + 255) / 256, 256>>>(x, wg);
    scan_kernel<<<1, 256>>>(out);

    // GEMM1: gathered x [CAP,H] @ w1[e] [H,F] -> gelu -> g_h [CAP,F]
    mma_gemm_kernel<true, true><<<dim3(F / 128, CAP / 128, E), 256>>>(
        x, w1, hbuf, H, F, 0, (size_t)H * F, (size_t)CAP * F);

    // GEMM2: g_h [CAP,F] @ w2[e] [F,H] -> g_eo [CAP,H]
    mma_gemm_kernel<false, false><<<dim3(H / 128, CAP / 128, E), 256>>>(
        hbuf, w2, eobuf, F, H, (size_t)CAP * F, (size_t)F * H, (size_t)CAP * H);

    combine_kernel<<<S, 256>>>(out);
}

// round 3
// speedup vs baseline: 2.5298x; 1.0004x over previous
#include <cuda_runtime.h>
#include <math.h>
#include <stdint.h>

// Problem constants (fixed by the dataset)
#define S 2048
#define H 1024
#define F 4096
#define E 8
#define CAP 512   // ceil(S*TOPK*CAP_FACTOR/E)

// ---------------- device scratch (no runtime allocation allowed) ----------------
__device__ float g_gates[S * E];
__device__ int   g_idx1[S];
__device__ int   g_idx2[S];
__device__ int   g_c1[S];
__device__ int   g_c2[S];
__device__ float g_w1s[S];
__device__ float g_w2s[S];
__device__ int   g_slot_tok[E * CAP];
__device__ float g_h[(size_t)E * CAP * F];    // 64 MB: gelu(dispatched @ w1)
__device__ float g_eo[(size_t)E * CAP * H];   // 16 MB: expert outputs

// ---------------- init: empty slots -> -1 ----------------
__global__ void init_kernel() {
    int i = blockIdx.x * blockDim.x + threadIdx.x;
    if (i < E * CAP) g_slot_tok[i] = -1;
}

// ---------------- gating: logits, softmax, top-2 ----------------
__global__ void gate_kernel(const float* __restrict__ x, const float* __restrict__ wg) {
    int warp = (blockIdx.x * blockDim.x + threadIdx.x) >> 5;
    int lane = threadIdx.x & 31;
    if (warp >= S) return;
    const float* xr = x + (size_t)warp * H;

    float acc[E];
#pragma unroll
    for (int e = 0; e < E; e++) acc[e] = 0.0f;

    for (int k = lane; k < H; k += 32) {
        float xv = xr[k];
        const float* wr = wg + (size_t)k * E;
#pragma unroll
        for (int e = 0; e < E; e++) acc[e] += xv * wr[e];
    }
#pragma unroll
    for (int off = 16; off > 0; off >>= 1) {
#pragma unroll
        for (int e = 0; e < E; e++)
            acc[e] += __shfl_down_sync(0xffffffffu, acc[e], off);
    }
    if (lane == 0) {
        float mx = acc[0];
#pragma unroll
        for (int e = 1; e < E; e++) mx = fmaxf(mx, acc[e]);
        float g[E], sum = 0.0f;
#pragma unroll
        for (int e = 0; e < E; e++) { g[e] = expf(acc[e] - mx); sum += g[e]; }
        float inv = 1.0f / sum;

        int i1 = 0; float v1 = acc[0];
#pragma unroll
        for (int e = 1; e < E; e++) if (acc[e] > v1) { v1 = acc[e]; i1 = e; }
        int i2 = -1; float v2 = -3.4e38f;
#pragma unroll
        for (int e = 0; e < E; e++)
            if (e != i1 && acc[e] > v2) { v2 = acc[e]; i2 = e; }

#pragma unroll
        for (int e = 0; e < E; e++) g_gates[warp * E + e] = g[e] * inv;
        g_idx1[warp] = i1;
        g_idx2[warp] = i2;
    }
}

// ---------------- scan: ranks, capacity drop, combine weights, aux ----------------
__global__ void scan_kernel(float* __restrict__ out) {
    __shared__ int   sh_count1[E];
    __shared__ float sh_me[E];
    int warp = threadIdx.x >> 5;
    int lane = threadIdx.x & 31;
    unsigned lt_mask = (lane == 0) ? 0u : (0xffffffffu >> (32 - lane));

    {
        int e = warp;
        int rank = 0;
        float mesum = 0.0f;
        for (int t0 = 0; t0 < S; t0 += 32) {
            int s = t0 + lane;
            int bit = (g_idx1[s] == e);
            unsigned m = __ballot_sync(0xffffffffu, bit);
            if (bit) {
                int r = rank + __popc(m & lt_mask);
                if (r < CAP) { g_c1[s] = r; g_slot_tok[e * CAP + r] = s; }
                else         { g_c1[s] = -1; }
            }
            rank += __popc(m);
            mesum += g_gates[s * E + e];
        }
#pragma unroll
        for (int off = 16; off > 0; off >>= 1)
            mesum += __shfl_down_sync(0xffffffffu, mesum, off);
        if (lane == 0) { sh_count1[e] = rank; sh_me[e] = mesum; }
    }
    __syncthreads();

    {
        int e = warp;
        int base = sh_count1[e];
        int rank = 0;
        for (int t0 = 0; t0 < S; t0 += 32) {
            int s = t0 + lane;
            int bit = (g_idx2[s] == e);
            unsigned m = __ballot_sync(0xffffffffu, bit);
            if (bit) {
                int r = base + rank + __popc(m & lt_mask);
                if (r < CAP) { g_c2[s] = r; g_slot_tok[e * CAP + r] = s; }
                else         { g_c2[s] = -1; }
            }
            rank += __popc(m);
        }
    }
    __syncthreads();

    for (int s = threadIdx.x; s < S; s += blockDim.x) {
        int i1 = g_idx1[s], i2 = g_idx2[s];
        float g1 = (g_c1[s] >= 0) ? g_gates[s * E + i1] : 0.0f;
        float g2 = (g_c2[s] >= 0) ? g_gates[s * E + i2] : 0.0f;
        float denom = fmaxf(g1 + g2, 1.1920929e-7f);
        g_w1s[s] = g1 / denom;
        g_w2s[s] = g2 / denom;
    }

    if (threadIdx.x == 0) {
        float laux = 0.0f;
        const float invS = 1.0f / (float)S;
#pragma unroll
        for (int e = 0; e < E; e++)
            laux += (sh_me[e] * invS) * ((float)sh_count1[e] * invS);
        laux = laux * (float)E * 0.01f;
        out[(size_t)S * H] = laux;
#pragma unroll
        for (int e = 0; e < E; e++)
            out[(size_t)S * H + 1 + e] = (float)sh_count1[e];
    }
}

// ---------------- TF32 tensor-core GEMM ----------------
__device__ __forceinline__ float gelu_tanh(float v) {
    const float c = 0.7978845608028654f;
    float t = tanhf(c * (v + 0.044715f * v * v * v));
    return 0.5f * v * (1.0f + t);
}

__device__ __forceinline__ uint32_t f2tf32(float f) {
    uint32_t r;
    asm("cvt.rna.tf32.f32 %0, %1;" : "=r"(r) : "f"(f));
    return r;
}

__device__ __forceinline__ void mma_tf32(float c[4], const uint32_t a[4], const uint32_t b[2]) {
    asm volatile(
        "mma.sync.aligned.m16n8k8.row.col.f32.tf32.tf32.f32 "
        "{%0,%1,%2,%3}, {%4,%5,%6,%7}, {%8,%9}, {%0,%1,%2,%3};\n"
        : "+f"(c[0]), "+f"(c[1]), "+f"(c[2]), "+f"(c[3])
        : "r"(a[0]), "r"(a[1]), "r"(a[2]), "r"(a[3]), "r"(b[0]), "r"(b[1]));
}

// Block tile 128x128, BK=16, 256 threads = 8 warps (2 M x 4 N), warp tile 64x32.
#define BK 16
#define APAD 8   // As row stride 136: conflict-free fragment loads
#define BPAD 8

template <bool GATHER, bool GELU>
__global__ void __launch_bounds__(256)
mma_gemm_kernel(const float* __restrict__ A, const float* __restrict__ B,
                float* __restrict__ Cmat, int K, int N,
                size_t strideA_e, size_t strideB_e, size_t strideC_e) {
    __shared__ uint32_t As[BK][128 + APAD];   // [k][m]
    __shared__ uint32_t Bs[BK][128 + BPAD];   // [k][n]

    int e = blockIdx.z;
    const float* Ae = GATHER ? A : (A + e * strideA_e);
    const float* Be = B + e * strideB_e;
    float* Ce = Cmat + e * strideC_e;

    int tid  = threadIdx.x;
    int m0   = blockIdx.y * 128;
    int n0   = blockIdx.x * 128;

    // ---- global load mapping ----
    // A tile: 128 rows x 16 cols. thread -> rows (tid/4) and (tid/4 + 64), k-offset (tid%4)*4
    int ar  = tid >> 2;            // 0..63
    int ak4 = (tid & 3) * 4;       // 0,4,8,12
    const float* Aptr0;
    const float* Aptr1;
    if (GATHER) {
        int t0 = g_slot_tok[e * CAP + m0 + ar];
        int t1 = g_slot_tok[e * CAP + m0 + ar + 64];
        Aptr0 = (t0 >= 0) ? (Ae + (size_t)t0 * K) : nullptr;
        Aptr1 = (t1 >= 0) ? (Ae + (size_t)t1 * K) : nullptr;
    } else {
        Aptr0 = Ae + (size_t)(m0 + ar) * K;
        Aptr1 = Ae + (size_t)(m0 + ar + 64) * K;
    }
    // B tile: 16 rows x 128 cols. thread -> k rows (tid/32) and (tid/32+8), col (tid%32)*4
    int bk  = tid >> 5;            // 0..7
    int bc  = (tid & 31) * 4;
    const float* Bptr = Be + (size_t)bk * N + n0 + bc;

    // ---- warp/fragment mapping ----
    int w      = tid >> 5;
    int lane   = tid & 31;
    int warp_m = (w & 1) * 64;     // 0 or 64
    int warp_n = (w >> 1) * 32;    // 0,32,64,96
    int group  = lane >> 2;        // 0..7
    int tg     = lane & 3;         // 0..3

    float acc[4][4][4];
#pragma unroll
    for (int i = 0; i < 4; i++)
#pragma unroll
        for (int j = 0; j < 4; j++)
#pragma unroll
            for (int r = 0; r < 4; r++) acc[i][j][r] = 0.0f;

    // prefetch first tile
    float4 pa0 = make_float4(0.f,0.f,0.f,0.f), pa1 = pa0, pb0, pb1;
    if (!GATHER || Aptr0) pa0 = *reinterpret_cast<const float4*>(Aptr0 + ak4);
    if (!GATHER || Aptr1) pa1 = *reinterpret_cast<const float4*>(Aptr1 + ak4);
    pb0 = *reinterpret_cast<const float4*>(Bptr);
    pb1 = *reinterpret_cast<const float4*>(Bptr + (size_t)8 * N);

    for (int k0 = 0; k0 < K; k0 += BK) {
        // store current tile to smem (tf32-rounded)
        As[ak4 + 0][ar]      = f2tf32(pa0.x);
        As[ak4 + 1][ar]      = f2tf32(pa0.y);
        As[ak4 + 2][ar]      = f2tf32(pa0.z);
        As[ak4 + 3][ar]      = f2tf32(pa0.w);
        As[ak4 + 0][ar + 64] = f2tf32(pa1.x);
        As[ak4 + 1][ar + 64] = f2tf32(pa1.y);
        As[ak4 + 2][ar + 64] = f2tf32(pa1.z);
        As[ak4 + 3][ar + 64] = f2tf32(pa1.w);
        Bs[bk][bc + 0]     = f2tf32(pb0.x);
        Bs[bk][bc + 1]     = f2tf32(pb0.y);
        Bs[bk][bc + 2]     = f2tf32(pb0.z);
        Bs[bk][bc + 3]     = f2tf32(pb0.w);
        Bs[bk + 8][bc + 0] = f2tf32(pb1.x);
        Bs[bk + 8][bc + 1] = f2tf32(pb1.y);
        Bs[bk + 8][bc + 2] = f2tf32(pb1.z);
        Bs[bk + 8][bc + 3] = f2tf32(pb1.w);
        __syncthreads();

        // prefetch next tile (overlaps with mma compute below)
        if (k0 + BK < K) {
            int kn = k0 + BK;
            if (!GATHER || Aptr0) pa0 = *reinterpret_cast<const float4*>(Aptr0 + kn + ak4);
            if (!GATHER || Aptr1) pa1 = *reinterpret_cast<const float4*>(Aptr1 + kn + ak4);
            pb0 = *reinterpret_cast<const float4*>(Bptr + (size_t)kn * N);
            pb1 = *reinterpret_cast<const float4*>(Bptr + (size_t)(kn + 8) * N);
        }

        // compute: 2 k-steps of 8
#pragma unroll
        for (int ks = 0; ks < 2; ks++) {
            int kb = ks * 8 + tg;
            uint32_t af[4][4];
#pragma unroll
            for (int i = 0; i < 4; i++) {
                int m = warp_m + i * 16 + group;
                af[i][0] = As[kb][m];
                af[i][1] = As[kb][m + 8];
                af[i][2] = As[kb + 4][m];
                af[i][3] = As[kb + 4][m + 8];
            }
            uint32_t bf[4][2];
#pragma unroll
            for (int j = 0; j < 4; j++) {
                int n = warp_n + j * 8 + group;
                bf[j][0] = Bs[kb][n];
                bf[j][1] = Bs[kb + 4][n];
            }
#pragma unroll
            for (int i = 0; i < 4; i++)
#pragma unroll
                for (int j = 0; j < 4; j++)
                    mma_tf32(acc[i][j], af[i], bf[j]);
        }
        __syncthreads();
    }

    // ---- epilogue ----
#pragma unroll
    for (int i = 0; i < 4; i++) {
        int row0 = m0 + warp_m + i * 16 + group;
#pragma unroll
        for (int j = 0; j < 4; j++) {
            int col = n0 + warp_n + j * 8 + tg * 2;
            float2 v0 = make_float2(acc[i][j][0], acc[i][j][1]);
            float2 v1 = make_float2(acc[i][j][2], acc[i][j][3]);
            if (GELU) {
                v0.x = gelu_tanh(v0.x); v0.y = gelu_tanh(v0.y);
                v1.x = gelu_tanh(v1.x); v1.y = gelu_tanh(v1.y);
            }
            *reinterpret_cast<float2*>(Ce + (size_t)row0 * N + col)       = v0;
            *reinterpret_cast<float2*>(Ce + (size_t)(row0 + 8) * N + col) = v1;
        }
    }
}

// ---------------- combine ----------------
__global__ void combine_kernel(float* __restrict__ out) {
    int s = blockIdx.x;
    int c1 = g_c1[s], c2 = g_c2[s];
    float w1 = g_w1s[s], w2 = g_w2s[s];
    const float* r1 = (c1 >= 0) ? (g_eo + ((size_t)g_idx1[s] * CAP + c1) * H) : nullptr;
    const float* r2 = (c2 >= 0) ? (g_eo + ((size_t)g_idx2[s] * CAP + c2) * H) : nullptr;

    int hh = threadIdx.x * 4;
    float4 v = make_float4(0.f, 0.f, 0.f, 0.f);
    if (r1) {
        float4 a = *reinterpret_cast<const float4*>(r1 + hh);
        v.x += w1 * a.x; v.y += w1 * a.y; v.z += w1 * a.z; v.w += w1 * a.w;
    }
    if (r2) {
        float4 a = *reinterpret_cast<const float4*>(r2 + hh);
        v.x += w2 * a.x; v.y += w2 * a.y; v.z += w2 * a.z; v.w += w2 * a.w;
    }
    *reinterpret_cast<float4*>(out + (size_t)s * H + hh) = v;
}

// ---------------- launch ----------------
extern "C" void kernel_launch(void* const* d_in, const int* in_sizes, int n_in,
                              void* d_out, int out_size) {
    const float* x  = (const float*)d_in[0];  // [S, H]
    const float* wg = (const float*)d_in[1];  // [H, E]
    const float* w1 = (const float*)d_in[2];  // [E, H, F]
    const float* w2 = (const float*)d_in[3];  // [E, F, H]
    float* out = (float*)d_out;

    float* hbuf = nullptr;
    float* eobuf = nullptr;
    cudaGetSymbolAddress((void**)&hbuf, g_h);
    cudaGetSymbolAddress((void**)&eobuf, g_eo);

    init_kernel<<<(E * CAP + 255) / 256, 256>>>();
    gate_kernel<<<(S * 32 + 255) / 256, 256>>>(x, wg);
    scan_kernel<<<1, 256>>>(out);

    // GEMM1: gathered x [CAP,H] @ w1[e] [H,F] -> gelu -> g_h [CAP,F]
    mma_gemm_kernel<true, true><<<dim3(F / 128, CAP / 128, E), 256>>>(
        x, w1, hbuf, H, F, 0, (size_t)H * F, (size_t)CAP * F);

    // GEMM2: g_h [CAP,F] @ w2[e] [F,H] -> g_eo [CAP,H]
    mma_gemm_kernel<false, false><<<dim3(H / 128, CAP / 128, E), 256>>>(
        hbuf, w2, eobuf, F, H, (size_t)CAP * F, (size_t)F * H, (size_t)CAP * H);

    combine_kernel<<<S, 256>>>(out);
}

// round 5
// speedup vs baseline: 2.8243x; 1.1164x over previous
#include <cuda_runtime.h>
#include <cuda_fp16.h>
#include <math.h>
#include <stdint.h>

#define S 2048
#define H 1024
#define F 4096
#define E 8
#define CAP 512
#define BM 256
#define BN 128
#define GK 16
#define ASTB 48    // As row stride bytes (24 halfs)
#define BSTB 528   // Bs row stride bytes (264 halfs)

__device__ float  g_gates[S * E];
__device__ int    g_idx1[S];
__device__ int    g_idx2[S];
__device__ int    g_c1[S];
__device__ int    g_c2[S];
__device__ float  g_w1s[S];
__device__ float  g_w2s[S];
__device__ int    g_slot_tok[E * CAP];
__device__ __half g_h[(size_t)E * CAP * F];    // 32 MB fp16
__device__ float  g_eo[(size_t)E * CAP * H];   // 16 MB

// ---------------- helpers ----------------
__device__ __forceinline__ uint32_t smem_u32(const void* p) {
    uint32_t a;
    asm("{ .reg .u64 t; cvta.to.shared.u64 t, %1; cvt.u32.u64 %0, t; }" : "=r"(a) : "l"(p));
    return a;
}
__device__ __forceinline__ void sts128(uint32_t a, uint32_t x, uint32_t y, uint32_t z, uint32_t w) {
    asm volatile("st.shared.v4.b32 [%0], {%1,%2,%3,%4};" :: "r"(a), "r"(x), "r"(y), "r"(z), "r"(w) : "memory");
}
__device__ __forceinline__ void ldsm4(uint32_t* r, uint32_t a) {
    asm volatile("ldmatrix.sync.aligned.m8n8.x4.shared.b16 {%0,%1,%2,%3}, [%4];"
                 : "=r"(r[0]), "=r"(r[1]), "=r"(r[2]), "=r"(r[3]) : "r"(a));
}
__device__ __forceinline__ void ldsm4t(uint32_t* r, uint32_t a) {
    asm volatile("ldmatrix.sync.aligned.m8n8.x4.trans.shared.b16 {%0,%1,%2,%3}, [%4];"
                 : "=r"(r[0]), "=r"(r[1]), "=r"(r[2]), "=r"(r[3]) : "r"(a));
}
__device__ __forceinline__ void mma16816(float* c, const uint32_t* a, const uint32_t* b) {
    asm volatile(
        "mma.sync.aligned.m16n8k16.row.col.f32.f16.f16.f32 "
        "{%0,%1,%2,%3}, {%4,%5,%6,%7}, {%8,%9}, {%0,%1,%2,%3};"
        : "+f"(c[0]), "+f"(c[1]), "+f"(c[2]), "+f"(c[3])
        : "r"(a[0]), "r"(a[1]), "r"(a[2]), "r"(a[3]), "r"(b[0]), "r"(b[1]));
}
__device__ __forceinline__ uint32_t h2u(float a, float b) {
    __half2 h = __floats2half2_rn(a, b);
    return *reinterpret_cast<uint32_t*>(&h);
}
__device__ __forceinline__ float gelu_tanh(float v) {
    const float c = 0.7978845608028654f;
    float t = tanhf(c * (v + 0.044715f * v * v * v));
    return 0.5f * v * (1.0f + t);
}

// ---------------- init / gate / scan (proven) ----------------
__global__ void init_kernel() {
    int i = blockIdx.x * blockDim.x + threadIdx.x;
    if (i < E * CAP) g_slot_tok[i] = -1;
}

__global__ void gate_kernel(const float* __restrict__ x, const float* __restrict__ wg) {
    int warp = (blockIdx.x * blockDim.x + threadIdx.x) >> 5;
    int lane = threadIdx.x & 31;
    if (warp >= S) return;
    const float* xr = x + (size_t)warp * H;
    float acc[E];
#pragma unroll
    for (int e = 0; e < E; e++) acc[e] = 0.0f;
    for (int k = lane; k < H; k += 32) {
        float xv = xr[k];
        const float* wr = wg + (size_t)k * E;
#pragma unroll
        for (int e = 0; e < E; e++) acc[e] += xv * wr[e];
    }
#pragma unroll
    for (int off = 16; off > 0; off >>= 1)
#pragma unroll
        for (int e = 0; e < E; e++)
            acc[e] += __shfl_down_sync(0xffffffffu, acc[e], off);
    if (lane == 0) {
        float mx = acc[0];
#pragma unroll
        for (int e = 1; e < E; e++) mx = fmaxf(mx, acc[e]);
        float g[E], sum = 0.0f;
#pragma unroll
        for (int e = 0; e < E; e++) { g[e] = expf(acc[e] - mx); sum += g[e]; }
        float inv = 1.0f / sum;
        int i1 = 0; float v1 = acc[0];
#pragma unroll
        for (int e = 1; e < E; e++) if (acc[e] > v1) { v1 = acc[e]; i1 = e; }
        int i2 = -1; float v2 = -3.4e38f;
#pragma unroll
        for (int e = 0; e < E; e++)
            if (e != i1 && acc[e] > v2) { v2 = acc[e]; i2 = e; }
#pragma unroll
        for (int e = 0; e < E; e++) g_gates[warp * E + e] = g[e] * inv;
        g_idx1[warp] = i1;
        g_idx2[warp] = i2;
    }
}

__global__ void scan_kernel(float* __restrict__ out) {
    __shared__ int   sh_count1[E];
    __shared__ float sh_me[E];
    int warp = threadIdx.x >> 5;
    int lane = threadIdx.x & 31;
    unsigned lt_mask = (lane == 0) ? 0u : (0xffffffffu >> (32 - lane));
    {
        int e = warp, rank = 0;
        float mesum = 0.0f;
        for (int t0 = 0; t0 < S; t0 += 32) {
            int s = t0 + lane;
            int bit = (g_idx1[s] == e);
            unsigned m = __ballot_sync(0xffffffffu, bit);
            if (bit) {
                int r = rank + __popc(m & lt_mask);
                if (r < CAP) { g_c1[s] = r; g_slot_tok[e * CAP + r] = s; }
                else         { g_c1[s] = -1; }
            }
            rank += __popc(m);
            mesum += g_gates[s * E + e];
        }
#pragma unroll
        for (int off = 16; off > 0; off >>= 1)
            mesum += __shfl_down_sync(0xffffffffu, mesum, off);
        if (lane == 0) { sh_count1[e] = rank; sh_me[e] = mesum; }
    }
    __syncthreads();
    {
        int e = warp, base = sh_count1[e], rank = 0;
        for (int t0 = 0; t0 < S; t0 += 32) {
            int s = t0 + lane;
            int bit = (g_idx2[s] == e);
            unsigned m = __ballot_sync(0xffffffffu, bit);
            if (bit) {
                int r = base + rank + __popc(m & lt_mask);
                if (r < CAP) { g_c2[s] = r; g_slot_tok[e * CAP + r] = s; }
                else         { g_c2[s] = -1; }
            }
            rank += __popc(m);
        }
    }
    __syncthreads();
    for (int s = threadIdx.x; s < S; s += blockDim.x) {
        int i1 = g_idx1[s], i2 = g_idx2[s];
        float g1 = (g_c1[s] >= 0) ? g_gates[s * E + i1] : 0.0f;
        float g2 = (g_c2[s] >= 0) ? g_gates[s * E + i2] : 0.0f;
        float denom = fmaxf(g1 + g2, 1.1920929e-7f);
        g_w1s[s] = g1 / denom;
        g_w2s[s] = g2 / denom;
    }
    if (threadIdx.x == 0) {
        float laux = 0.0f;
        const float invS = 1.0f / (float)S;
#pragma unroll
        for (int e = 0; e < E; e++)
            laux += (sh_me[e] * invS) * ((float)sh_count1[e] * invS);
        laux = laux * (float)E * 0.01f;
        out[(size_t)S * H] = laux;
#pragma unroll
        for (int e = 0; e < E; e++)
            out[(size_t)S * H + 1 + e] = (float)sh_count1[e];
    }
}

// ---------------- fp16 tensor-core GEMM (ldmatrix + mma.m16n8k16) ----------------
// Block 256x128, BK=16. 8 warps (4M x 2N), warp tile 64x64.
// MODE 1: A = gathered fp32 x, C = fp16 g_h with GELU.  MODE 2: A = fp16, C = fp32.
template <int MODE>
__global__ void __launch_bounds__(256, 1)
hgemm_kernel(const void* __restrict__ Av, const float* __restrict__ B,
             void* __restrict__ Cv, int K, int N,
             size_t sAe, size_t sBe, size_t sCe) {
    __shared__ __align__(16) __half As[BM * 24];   // 12288 B
    __shared__ __align__(16) __half Bs[GK * 264];  //  8448 B

    int tid = threadIdx.x;
    int e = blockIdx.z;
    int m0 = blockIdx.y * BM;
    int n0 = blockIdx.x * BN;
    const float* Be = B + e * sBe;

    // A loader: thread = one row
    const float* aF = nullptr;
    const __half* aH = nullptr;
    if (MODE == 1) {
        int tok = g_slot_tok[e * CAP + m0 + tid];
        aF = (tok >= 0) ? ((const float*)Av + (size_t)tok * K) : nullptr;
    } else {
        aH = (const __half*)Av + e * sAe + (size_t)(m0 + tid) * K;
    }
    // B loader: bk = tid>>4 (k row), bc = (tid&15)*8 (n offset)
    const float* bptr = Be + (size_t)(tid >> 4) * N + n0 + (tid & 15) * 8;

    int w = tid >> 5, lane = tid & 31;
    int wm = (w >> 1) * 64, wn = (w & 1) * 64;
    uint32_t asb = smem_u32(As), bsb = smem_u32(Bs);
    uint32_t a_addr = asb + (uint32_t)(wm + (lane & 15)) * ASTB + (lane >> 4) * 16;
    uint32_t b_addr = bsb + (uint32_t)((lane & 7) + ((lane >> 3) & 1) * 8) * BSTB
                          + (uint32_t)(wn + (lane >> 4) * 8) * 2;
    uint32_t a_sts = asb + (uint32_t)tid * ASTB;
    uint32_t b_sts = bsb + (uint32_t)(tid >> 4) * BSTB + (uint32_t)(tid & 15) * 16;

    float acc[4][8][4];
#pragma unroll
    for (int i = 0; i < 4; i++)
#pragma unroll
        for (int j = 0; j < 8; j++)
#pragma unroll
            for (int r = 0; r < 4; r++) acc[i][j][r] = 0.0f;

    uint32_t pa[8], pb[4];
    // prefetch tile 0
    {
        if (MODE == 1) {
            float4 z = make_float4(0.f, 0.f, 0.f, 0.f);
            float4 a0 = z, a1 = z, a2 = z, a3 = z;
            if (aF) {
                a0 = *reinterpret_cast<const float4*>(aF + 0);
                a1 = *reinterpret_cast<const float4*>(aF + 4);
                a2 = *reinterpret_cast<const float4*>(aF + 8);
                a3 = *reinterpret_cast<const float4*>(aF + 12);
            }
            pa[0] = h2u(a0.x, a0.y); pa[1] = h2u(a0.z, a0.w);
            pa[2] = h2u(a1.x, a1.y); pa[3] = h2u(a1.z, a1.w);
            pa[4] = h2u(a2.x, a2.y); pa[5] = h2u(a2.z, a2.w);
            pa[6] = h2u(a3.x, a3.y); pa[7] = h2u(a3.z, a3.w);
        } else {
            uint4 v0 = *reinterpret_cast<const uint4*>(aH);
            uint4 v1 = *reinterpret_cast<const uint4*>(aH + 8);
            pa[0] = v0.x; pa[1] = v0.y; pa[2] = v0.z; pa[3] = v0.w;
            pa[4] = v1.x; pa[5] = v1.y; pa[6] = v1.z; pa[7] = v1.w;
        }
        float4 b0 = *reinterpret_cast<const float4*>(bptr);
        float4 b1 = *reinterpret_cast<const float4*>(bptr + 4);
        pb[0] = h2u(b0.x, b0.y); pb[1] = h2u(b0.z, b0.w);
        pb[2] = h2u(b1.x, b1.y); pb[3] = h2u(b1.z, b1.w);
    }

    for (int k0 = 0; k0 < K; k0 += GK) {
        sts128(a_sts,      pa[0], pa[1], pa[2], pa[3]);
        sts128(a_sts + 16, pa[4], pa[5], pa[6], pa[7]);
        sts128(b_sts,      pb[0], pb[1], pb[2], pb[3]);
        __syncthreads();

        if (k0 + GK < K) {
            int kn = k0 + GK;
            if (MODE == 1) {
                float4 z = make_float4(0.f, 0.f, 0.f, 0.f);
                float4 a0 = z, a1 = z, a2 = z, a3 = z;
                if (aF) {
                    a0 = *reinterpret_cast<const float4*>(aF + kn + 0);
                    a1 = *reinterpret_cast<const float4*>(aF + kn + 4);
                    a2 = *reinterpret_cast<const float4*>(aF + kn + 8);
                    a3 = *reinterpret_cast<const float4*>(aF + kn + 12);
                }
                pa[0] = h2u(a0.x, a0.y); pa[1] = h2u(a0.z, a0.w);
                pa[2] = h2u(a1.x, a1.y); pa[3] = h2u(a1.z, a1.w);
                pa[4] = h2u(a2.x, a2.y); pa[5] = h2u(a2.z, a2.w);
                pa[6] = h2u(a3.x, a3.y); pa[7] = h2u(a3.z, a3.w);
            } else {
                uint4 v0 = *reinterpret_cast<const uint4*>(aH + kn);
                uint4 v1 = *reinterpret_cast<const uint4*>(aH + kn + 8);
                pa[0] = v0.x; pa[1] = v0.y; pa[2] = v0.z; pa[3] = v0.w;
                pa[4] = v1.x; pa[5] = v1.y; pa[6] = v1.z; pa[7] = v1.w;
            }
            float4 b0 = *reinterpret_cast<const float4*>(bptr + (size_t)kn * N);
            float4 b1 = *reinterpret_cast<const float4*>(bptr + (size_t)kn * N + 4);
            pb[0] = h2u(b0.x, b0.y); pb[1] = h2u(b0.z, b0.w);
            pb[2] = h2u(b1.x, b1.y); pb[3] = h2u(b1.z, b1.w);
        }

        uint32_t af[4][4];
#pragma unroll
        for (int i = 0; i < 4; i++) ldsm4(af[i], a_addr + i * (16 * ASTB));
        uint32_t bf[8][2];
#pragma unroll
        for (int jp = 0; jp < 4; jp++) {
            uint32_t r[4];
            ldsm4t(r, b_addr + jp * 32);
            bf[2 * jp][0] = r[0]; bf[2 * jp][1] = r[1];
            bf[2 * jp + 1][0] = r[2]; bf[2 * jp + 1][1] = r[3];
        }
#pragma unroll
        for (int i = 0; i < 4; i++)
#pragma unroll
            for (int j = 0; j < 8; j++)
                mma16816(acc[i][j], af[i], bf[j]);
        __syncthreads();
    }

    // ---- epilogue ----
    int gq = lane >> 2, tq = lane & 3;
#pragma unroll
    for (int i = 0; i < 4; i++) {
        int row = m0 + wm + i * 16 + gq;
#pragma unroll
        for (int j = 0; j < 8; j++) {
            int col = n0 + wn + j * 8 + tq * 2;
            if (MODE == 1) {
                __half* Ch = (__half*)Cv + e * sCe;
                __half2 v0 = __floats2half2_rn(gelu_tanh(acc[i][j][0]), gelu_tanh(acc[i][j][1]));
                __half2 v1 = __floats2half2_rn(gelu_tanh(acc[i][j][2]), gelu_tanh(acc[i][j][3]));
                *reinterpret_cast<__half2*>(Ch + (size_t)row * N + col) = v0;
                *reinterpret_cast<__half2*>(Ch + (size_t)(row + 8) * N + col) = v1;
            } else {
                float* Cf = (float*)Cv + e * sCe;
                *reinterpret_cast<float2*>(Cf + (size_t)row * N + col) =
                    make_float2(acc[i][j][0], acc[i][j][1]);
                *reinterpret_cast<float2*>(Cf + (size_t)(row + 8) * N + col) =
                    make_float2(acc[i][j][2], acc[i][j][3]);
            }
        }
    }
}

// ---------------- combine ----------------
__global__ void combine_kernel(float* __restrict__ out) {
    int s = blockIdx.x;
    int c1 = g_c1[s], c2 = g_c2[s];
    float w1 = g_w1s[s], w2 = g_w2s[s];
    const float* r1 = (c1 >= 0) ? (g_eo + ((size_t)g_idx1[s] * CAP + c1) * H) : nullptr;
    const float* r2 = (c2 >= 0) ? (g_eo + ((size_t)g_idx2[s] * CAP + c2) * H) : nullptr;
    int hh = threadIdx.x * 4;
    float4 v = make_float4(0.f, 0.f, 0.f, 0.f);
    if (r1) {
        float4 a = *reinterpret_cast<const float4*>(r1 + hh);
        v.x += w1 * a.x; v.y += w1 * a.y; v.z += w1 * a.z; v.w += w1 * a.w;
    }
    if (r2) {
        float4 a = *reinterpret_cast<const float4*>(r2 + hh);
        v.x += w2 * a.x; v.y += w2 * a.y; v.z += w2 * a.z; v.w += w2 * a.w;
    }
    *reinterpret_cast<float4*>(out + (size_t)s * H + hh) = v;
}

// ---------------- launch ----------------
extern "C" void kernel_launch(void* const* d_in, const int* in_sizes, int n_in,
                              void* d_out, int out_size) {
    const float* x  = (const float*)d_in[0];
    const float* wg = (const float*)d_in[1];
    const float* w1 = (const float*)d_in[2];
    const float* w2 = (const float*)d_in[3];
    float* out = (float*)d_out;

    __half* hbuf = nullptr;
    float*  eobuf = nullptr;
    cudaGetSymbolAddress((void**)&hbuf, g_h);
    cudaGetSymbolAddress((void**)&eobuf, g_eo);

    init_kernel<<<(E * CAP + 255) / 256, 256>>>();
    gate_kernel<<<(S * 32 + 255) / 256, 256>>>(x, wg);
    scan_kernel<<<1, 256>>>(out);

    // GEMM1: gathered x [CAP,H] @ w1[e][H,F] -> gelu -> g_h (fp16)
    hgemm_kernel<1><<<dim3(F / BN, CAP / BM, E), 256>>>(
        x, w1, hbuf, H, F, 0, (size_t)H * F, (size_t)CAP * F);

    // GEMM2: g_h [CAP,F] fp16 @ w2[e][F,H] -> g_eo (fp32)
    hgemm_kernel<2><<<dim3(H / BN, CAP / BM, E), 256>>>(
        hbuf, w2, eobuf, F, H, (size_t)CAP * F, (size_t)F * H, (size_t)CAP * H);

    combine_kernel<<<S, 256>>>(out);
}

// round 6
// speedup vs baseline: 4.2970x; 1.5214x over previous
#include <cuda_runtime.h>
#include <cuda_fp16.h>
#include <math.h>
#include <stdint.h>

#define S 2048
#define H 1024
#define F 4096
#define E 8
#define CAP 512
#define BM 128
#define BN 128
#define BKT 32

// smem strides (bytes)
#define ASTB 80            // 32 halfs + 8 pad
#define BSTB 272           // 128 halfs + 8 pad
#define A_BYTES (BM * ASTB)            // 10240
#define STAGE (A_BYTES + BKT * BSTB)   // 10240 + 8704 = 18944
#define NSTAGE 3

__device__ float  g_gates[S * E];
__device__ int    g_idx1[S];
__device__ int    g_idx2[S];
__device__ int    g_c1[S];
__device__ int    g_c2[S];
__device__ float  g_w1s[S];
__device__ float  g_w2s[S];
__device__ int    g_slot_tok[E * CAP];
__device__ __half g_xh[(size_t)S * H];          //  4 MB
__device__ __half g_w1h[(size_t)E * H * F];     // 67 MB
__device__ __half g_w2h[(size_t)E * F * H];     // 67 MB
__device__ __half g_h[(size_t)E * CAP * F];     // 32 MB
__device__ float  g_eo[(size_t)E * CAP * H];    // 16 MB

// ---------------- helpers ----------------
__device__ __forceinline__ uint32_t smem_u32(const void* p) {
    uint32_t a;
    asm("{ .reg .u64 t; cvta.to.shared.u64 t, %1; cvt.u32.u64 %0, t; }" : "=r"(a) : "l"(p));
    return a;
}
__device__ __forceinline__ void cp16(uint32_t dst, const void* src) {
    asm volatile("cp.async.cg.shared.global [%0], [%1], 16;" :: "r"(dst), "l"(src));
}
__device__ __forceinline__ void cp16z(uint32_t dst, const void* src, int srcsize) {
    asm volatile("cp.async.cg.shared.global [%0], [%1], 16, %2;"
                 :: "r"(dst), "l"(src), "r"(srcsize));
}
__device__ __forceinline__ void cp_commit() {
    asm volatile("cp.async.commit_group;" ::: "memory");
}
template <int N> __device__ __forceinline__ void cp_wait() {
    asm volatile("cp.async.wait_group %0;" :: "n"(N) : "memory");
}
__device__ __forceinline__ void ldsm4(uint32_t* r, uint32_t a) {
    asm volatile("ldmatrix.sync.aligned.m8n8.x4.shared.b16 {%0,%1,%2,%3}, [%4];"
                 : "=r"(r[0]), "=r"(r[1]), "=r"(r[2]), "=r"(r[3]) : "r"(a));
}
__device__ __forceinline__ void ldsm4t(uint32_t* r, uint32_t a) {
    asm volatile("ldmatrix.sync.aligned.m8n8.x4.trans.shared.b16 {%0,%1,%2,%3}, [%4];"
                 : "=r"(r[0]), "=r"(r[1]), "=r"(r[2]), "=r"(r[3]) : "r"(a));
}
__device__ __forceinline__ void mma16816(float* c, const uint32_t* a, const uint32_t* b) {
    asm volatile(
        "mma.sync.aligned.m16n8k16.row.col.f32.f16.f16.f32 "
        "{%0,%1,%2,%3}, {%4,%5,%6,%7}, {%8,%9}, {%0,%1,%2,%3};"
        : "+f"(c[0]), "+f"(c[1]), "+f"(c[2]), "+f"(c[3])
        : "r"(a[0]), "r"(a[1]), "r"(a[2]), "r"(a[3]), "r"(b[0]), "r"(b[1]));
}
__device__ __forceinline__ float gelu_tanh(float v) {
    const float c = 0.7978845608028654f;
    float t = tanhf(c * (v + 0.044715f * v * v * v));
    return 0.5f * v * (1.0f + t);
}

// ---------------- fp32 -> fp16 convert ----------------
__global__ void cvt_kernel(const float4* __restrict__ src, __half2* __restrict__ dst, int n4) {
    int i = blockIdx.x * blockDim.x + threadIdx.x;
    if (i >= n4) return;
    float4 v = src[i];
    dst[2 * i]     = __floats2half2_rn(v.x, v.y);
    dst[2 * i + 1] = __floats2half2_rn(v.z, v.w);
}

// ---------------- init / gate / scan (proven) ----------------
__global__ void init_kernel() {
    int i = blockIdx.x * blockDim.x + threadIdx.x;
    if (i < E * CAP) g_slot_tok[i] = -1;
}

__global__ void gate_kernel(const float* __restrict__ x, const float* __restrict__ wg) {
    int warp = (blockIdx.x * blockDim.x + threadIdx.x) >> 5;
    int lane = threadIdx.x & 31;
    if (warp >= S) return;
    const float* xr = x + (size_t)warp * H;
    float acc[E];
#pragma unroll
    for (int e = 0; e < E; e++) acc[e] = 0.0f;
    for (int k = lane; k < H; k += 32) {
        float xv = xr[k];
        const float* wr = wg + (size_t)k * E;
#pragma unroll
        for (int e = 0; e < E; e++) acc[e] += xv * wr[e];
    }
#pragma unroll
    for (int off = 16; off > 0; off >>= 1)
#pragma unroll
        for (int e = 0; e < E; e++)
            acc[e] += __shfl_down_sync(0xffffffffu, acc[e], off);
    if (lane == 0) {
        float mx = acc[0];
#pragma unroll
        for (int e = 1; e < E; e++) mx = fmaxf(mx, acc[e]);
        float g[E], sum = 0.0f;
#pragma unroll
        for (int e = 0; e < E; e++) { g[e] = expf(acc[e] - mx); sum += g[e]; }
        float inv = 1.0f / sum;
        int i1 = 0; float v1 = acc[0];
#pragma unroll
        for (int e = 1; e < E; e++) if (acc[e] > v1) { v1 = acc[e]; i1 = e; }
        int i2 = -1; float v2 = -3.4e38f;
#pragma unroll
        for (int e = 0; e < E; e++)
            if (e != i1 && acc[e] > v2) { v2 = acc[e]; i2 = e; }
#pragma unroll
        for (int e = 0; e < E; e++) g_gates[warp * E + e] = g[e] * inv;
        g_idx1[warp] = i1;
        g_idx2[warp] = i2;
    }
}

__global__ void scan_kernel(float* __restrict__ out) {
    __shared__ int   sh_count1[E];
    __shared__ float sh_me[E];
    int warp = threadIdx.x >> 5;
    int lane = threadIdx.x & 31;
    unsigned lt_mask = (lane == 0) ? 0u : (0xffffffffu >> (32 - lane));
    {
        int e = warp, rank = 0;
        float mesum = 0.0f;
        for (int t0 = 0; t0 < S; t0 += 32) {
            int s = t0 + lane;
            int bit = (g_idx1[s] == e);
            unsigned m = __ballot_sync(0xffffffffu, bit);
            if (bit) {
                int r = rank + __popc(m & lt_mask);
                if (r < CAP) { g_c1[s] = r; g_slot_tok[e * CAP + r] = s; }
                else         { g_c1[s] = -1; }
            }
            rank += __popc(m);
            mesum += g_gates[s * E + e];
        }
#pragma unroll
        for (int off = 16; off > 0; off >>= 1)
            mesum += __shfl_down_sync(0xffffffffu, mesum, off);
        if (lane == 0) { sh_count1[e] = rank; sh_me[e] = mesum; }
    }
    __syncthreads();
    {
        int e = warp, base = sh_count1[e], rank = 0;
        for (int t0 = 0; t0 < S; t0 += 32) {
            int s = t0 + lane;
            int bit = (g_idx2[s] == e);
            unsigned m = __ballot_sync(0xffffffffu, bit);
            if (bit) {
                int r = base + rank + __popc(m & lt_mask);
                if (r < CAP) { g_c2[s] = r; g_slot_tok[e * CAP + r] = s; }
                else         { g_c2[s] = -1; }
            }
            rank += __popc(m);
        }
    }
    __syncthreads();
    for (int s = threadIdx.x; s < S; s += blockDim.x) {
        int i1 = g_idx1[s], i2 = g_idx2[s];
        float g1 = (g_c1[s] >= 0) ? g_gates[s * E + i1] : 0.0f;
        float g2 = (g_c2[s] >= 0) ? g_gates[s * E + i2] : 0.0f;
        float denom = fmaxf(g1 + g2, 1.1920929e-7f);
        g_w1s[s] = g1 / denom;
        g_w2s[s] = g2 / denom;
    }
    if (threadIdx.x == 0) {
        float laux = 0.0f;
        const float invS = 1.0f / (float)S;
#pragma unroll
        for (int e = 0; e < E; e++)
            laux += (sh_me[e] * invS) * ((float)sh_count1[e] * invS);
        laux = laux * (float)E * 0.01f;
        out[(size_t)S * H] = laux;
#pragma unroll
        for (int e = 0; e < E; e++)
            out[(size_t)S * H + 1 + e] = (float)sh_count1[e];
    }
}

// ---------------- fp16 GEMM: cp.async 3-stage + ldmatrix + mma.m16n8k16 ----------------
// Block 128x128, BK=32, 8 warps (2M x 4N), warp tile 64x32.
// MODE 1: A = g_xh gathered, C = g_h (fp16, GELU).  MODE 2: A = fp16 dense, C = fp32.
template <int MODE>
__global__ void __launch_bounds__(256, 2)
hgemm_async(const __half* __restrict__ Ah, const __half* __restrict__ Bh,
            void* __restrict__ Cv, int K, int N,
            size_t sAe, size_t sBe, size_t sCe) {
    extern __shared__ __align__(16) char smem[];
    const uint32_t sb = smem_u32(smem);

    int tid = threadIdx.x;
    int e = blockIdx.z;
    int m0 = blockIdx.y * BM;
    int n0 = blockIdx.x * BN;
    const __half* Be = Bh + e * sBe;

    // ---- loader mapping ----
    // A: thread t -> row t>>1, 2 chunks of 16B at (t&1)*32B
    int arow = tid >> 1;
    int acs  = (tid & 1) * 2;   // chunk pair index (halfs offset = acs*8)
    const __half* a_src;
    int asz = 16;
    if (MODE == 1) {
        int tok = g_slot_tok[e * CAP + m0 + arow];
        a_src = (tok >= 0) ? (Ah + (size_t)tok * K) : Ah;
        asz = (tok >= 0) ? 16 : 0;
    } else {
        a_src = Ah + e * sAe + (size_t)(m0 + arow) * K;
    }
    uint32_t a_dst = sb + (uint32_t)arow * ASTB + (uint32_t)acs * 16;
    // B: thread t -> k row t>>3, 2 chunks at (t&7)*32B
    int brow = tid >> 3;
    int bcs  = (tid & 7) * 2;
    const __half* b_src = Be + (size_t)brow * N + n0 + bcs * 8;
    uint32_t b_dst = sb + A_BYTES + (uint32_t)brow * BSTB + (uint32_t)bcs * 16;

    // ---- fragment mapping ----
    int w = tid >> 5, lane = tid & 31;
    int wm = (w >> 2) * 64;    // 0,64
    int wn = (w & 3) * 32;     // 0,32,64,96
    uint32_t a_frag = sb + (uint32_t)(wm + (lane & 15)) * ASTB + (uint32_t)(lane >> 4) * 16;
    uint32_t b_frag = sb + A_BYTES + (uint32_t)((lane & 7) + ((lane >> 3) & 1) * 8) * BSTB
                         + (uint32_t)(wn + (lane >> 4) * 8) * 2;

    float acc[4][4][4];
#pragma unroll
    for (int i = 0; i < 4; i++)
#pragma unroll
        for (int j = 0; j < 4; j++)
#pragma unroll
            for (int r = 0; r < 4; r++) acc[i][j][r] = 0.0f;

    int ntiles = K / BKT;

    // issue one stage's loads
    auto load_stage = [&](int buf, int k0) {
        uint32_t so = (uint32_t)buf * STAGE;
        const __half* as = a_src + k0 + acs * 8;
        if (MODE == 1) {
            cp16z(a_dst + so, as, asz);
            cp16z(a_dst + so + 16, as + 8, asz);
        } else {
            cp16(a_dst + so, as);
            cp16(a_dst + so + 16, as + 8);
        }
        const __half* bs = b_src + (size_t)k0 * N;
        cp16(b_dst + so, bs);
        cp16(b_dst + so + 16, bs + 8);
    };

    load_stage(0, 0); cp_commit();
    if (ntiles > 1) { load_stage(1, BKT); cp_commit(); }

    for (int it = 0; it < ntiles; it++) {
        if (it + 2 < ntiles) load_stage((it + 2) % NSTAGE, (it + 2) * BKT);
        cp_commit();
        cp_wait<2>();
        __syncthreads();

        uint32_t so = (uint32_t)(it % NSTAGE) * STAGE;
#pragma unroll
        for (int ks = 0; ks < 2; ks++) {
            uint32_t af[4][4];
#pragma unroll
            for (int i = 0; i < 4; i++)
                ldsm4(af[i], a_frag + so + (uint32_t)i * (16 * ASTB) + ks * 32);
            uint32_t bf[4][2];
#pragma unroll
            for (int jp = 0; jp < 2; jp++) {
                uint32_t r[4];
                ldsm4t(r, b_frag + so + (uint32_t)ks * (16 * BSTB) + jp * 32);
                bf[2 * jp][0] = r[0]; bf[2 * jp][1] = r[1];
                bf[2 * jp + 1][0] = r[2]; bf[2 * jp + 1][1] = r[3];
            }
#pragma unroll
            for (int i = 0; i < 4; i++)
#pragma unroll
                for (int j = 0; j < 4; j++)
                    mma16816(acc[i][j], af[i], bf[j]);
        }
        __syncthreads();
    }

    // ---- epilogue ----
    int gq = lane >> 2, tq = lane & 3;
#pragma unroll
    for (int i = 0; i < 4; i++) {
        int row = m0 + wm + i * 16 + gq;
#pragma unroll
        for (int j = 0; j < 4; j++) {
            int col = n0 + wn + j * 8 + tq * 2;
            if (MODE == 1) {
                __half* Ch = (__half*)Cv + e * sCe;
                __half2 v0 = __floats2half2_rn(gelu_tanh(acc[i][j][0]), gelu_tanh(acc[i][j][1]));
                __half2 v1 = __floats2half2_rn(gelu_tanh(acc[i][j][2]), gelu_tanh(acc[i][j][3]));
                *reinterpret_cast<__half2*>(Ch + (size_t)row * N + col) = v0;
                *reinterpret_cast<__half2*>(Ch + (size_t)(row + 8) * N + col) = v1;
            } else {
                float* Cf = (float*)Cv + e * sCe;
                *reinterpret_cast<float2*>(Cf + (size_t)row * N + col) =
                    make_float2(acc[i][j][0], acc[i][j][1]);
                *reinterpret_cast<float2*>(Cf + (size_t)(row + 8) * N + col) =
                    make_float2(acc[i][j][2], acc[i][j][3]);
            }
        }
    }
}

// ---------------- combine ----------------
__global__ void combine_kernel(float* __restrict__ out) {
    int s = blockIdx.x;
    int c1 = g_c1[s], c2 = g_c2[s];
    float w1 = g_w1s[s], w2 = g_w2s[s];
    const float* r1 = (c1 >= 0) ? (g_eo + ((size_t)g_idx1[s] * CAP + c1) * H) : nullptr;
    const float* r2 = (c2 >= 0) ? (g_eo + ((size_t)g_idx2[s] * CAP + c2) * H) : nullptr;
    int hh = threadIdx.x * 4;
    float4 v = make_float4(0.f, 0.f, 0.f, 0.f);
    if (r1) {
        float4 a = *reinterpret_cast<const float4*>(r1 + hh);
        v.x += w1 * a.x; v.y += w1 * a.y; v.z += w1 * a.z; v.w += w1 * a.w;
    }
    if (r2) {
        float4 a = *reinterpret_cast<const float4*>(r2 + hh);
        v.x += w2 * a.x; v.y += w2 * a.y; v.z += w2 * a.z; v.w += w2 * a.w;
    }
    *reinterpret_cast<float4*>(out + (size_t)s * H + hh) = v;
}

// ---------------- launch ----------------
extern "C" void kernel_launch(void* const* d_in, const int* in_sizes, int n_in,
                              void* d_out, int out_size) {
    const float* x  = (const float*)d_in[0];
    const float* wg = (const float*)d_in[1];
    const float* w1 = (const float*)d_in[2];
    const float* w2 = (const float*)d_in[3];
    float* out = (float*)d_out;

    __half *xh, *w1h, *w2h, *hbuf;
    float* eobuf;
    cudaGetSymbolAddress((void**)&xh,  g_xh);
    cudaGetSymbolAddress((void**)&w1h, g_w1h);
    cudaGetSymbolAddress((void**)&w2h, g_w2h);
    cudaGetSymbolAddress((void**)&hbuf, g_h);
    cudaGetSymbolAddress((void**)&eobuf, g_eo);

    const int SMEM = NSTAGE * STAGE;   // 56832
    cudaFuncSetAttribute(hgemm_async<1>, cudaFuncAttributeMaxDynamicSharedMemorySize, SMEM);
    cudaFuncSetAttribute(hgemm_async<2>, cudaFuncAttributeMaxDynamicSharedMemorySize, SMEM);

    // converts
    {
        int n4 = S * H / 4;
        cvt_kernel<<<(n4 + 255) / 256, 256>>>((const float4*)x, (__half2*)xh, n4);
        n4 = E * H * F / 4;
        cvt_kernel<<<(n4 + 255) / 256, 256>>>((const float4*)w1, (__half2*)w1h, n4);
        cvt_kernel<<<(n4 + 255) / 256, 256>>>((const float4*)w2, (__half2*)w2h, n4);
    }

    init_kernel<<<(E * CAP + 255) / 256, 256>>>();
    gate_kernel<<<(S * 32 + 255) / 256, 256>>>(x, wg);
    scan_kernel<<<1, 256>>>(out);

    // GEMM1: gathered xh [CAP,H] @ w1h[e][H,F] -> gelu -> g_h (fp16)
    hgemm_async<1><<<dim3(F / BN, CAP / BM, E), 256, SMEM>>>(
        xh, w1h, hbuf, H, F, 0, (size_t)H * F, (size_t)CAP * F);

    // GEMM2: g_h [CAP,F] @ w2h[e][F,H] -> g_eo (fp32)
    hgemm_async<2><<<dim3(H / BN, CAP / BM, E), 256, SMEM>>>(
        hbuf, w2h, eobuf, F, H, (size_t)CAP * F, (size_t)F * H, (size_t)CAP * H);

    combine_kernel<<<S, 256>>>(out);
}

// round 7
// speedup vs baseline: 4.3655x; 1.0159x over previous
#include <cuda_runtime.h>
#include <cuda_fp16.h>
#include <math.h>
#include <stdint.h>

#define S 2048
#define H 1024
#define F 4096
#define E 8
#define CAP 512
#define BM 128
#define BN 128
#define BKT 32

// smem strides (bytes)
#define ASTB 80            // 32 halfs + 8 pad
#define BSTB 272           // 128 halfs + 8 pad
#define A_BYTES (BM * ASTB)            // 10240
#define STAGE (A_BYTES + BKT * BSTB)   // 18944
#define NSTAGE 4

__device__ float  g_gates[S * E];
__device__ int    g_idx1[S];
__device__ int    g_idx2[S];
__device__ int    g_c1[S];
__device__ int    g_c2[S];
__device__ int    g_slot_tok[E * CAP];
__device__ float  g_slot_w[E * CAP];
__device__ __half g_xh[(size_t)S * H];          //  4 MB
__device__ __half g_w1h[(size_t)E * H * F];     // 67 MB
__device__ __half g_w2h[(size_t)E * F * H];     // 67 MB
__device__ __half g_h[(size_t)E * CAP * F];     // 33 MB

// ---------------- helpers ----------------
__device__ __forceinline__ uint32_t smem_u32(const void* p) {
    uint32_t a;
    asm("{ .reg .u64 t; cvta.to.shared.u64 t, %1; cvt.u32.u64 %0, t; }" : "=r"(a) : "l"(p));
    return a;
}
__device__ __forceinline__ void cp16(uint32_t dst, const void* src) {
    asm volatile("cp.async.cg.shared.global [%0], [%1], 16;" :: "r"(dst), "l"(src));
}
__device__ __forceinline__ void cp16z(uint32_t dst, const void* src, int srcsize) {
    asm volatile("cp.async.cg.shared.global [%0], [%1], 16, %2;"
                 :: "r"(dst), "l"(src), "r"(srcsize));
}
__device__ __forceinline__ void cp_commit() {
    asm volatile("cp.async.commit_group;" ::: "memory");
}
template <int N> __device__ __forceinline__ void cp_wait() {
    asm volatile("cp.async.wait_group %0;" :: "n"(N) : "memory");
}
__device__ __forceinline__ void ldsm4(uint32_t* r, uint32_t a) {
    asm volatile("ldmatrix.sync.aligned.m8n8.x4.shared.b16 {%0,%1,%2,%3}, [%4];"
                 : "=r"(r[0]), "=r"(r[1]), "=r"(r[2]), "=r"(r[3]) : "r"(a));
}
__device__ __forceinline__ void ldsm4t(uint32_t* r, uint32_t a) {
    asm volatile("ldmatrix.sync.aligned.m8n8.x4.trans.shared.b16 {%0,%1,%2,%3}, [%4];"
                 : "=r"(r[0]), "=r"(r[1]), "=r"(r[2]), "=r"(r[3]) : "r"(a));
}
__device__ __forceinline__ void mma16816(float* c, const uint32_t* a, const uint32_t* b) {
    asm volatile(
        "mma.sync.aligned.m16n8k16.row.col.f32.f16.f16.f32 "
        "{%0,%1,%2,%3}, {%4,%5,%6,%7}, {%8,%9}, {%0,%1,%2,%3};"
        : "+f"(c[0]), "+f"(c[1]), "+f"(c[2]), "+f"(c[3])
        : "r"(a[0]), "r"(a[1]), "r"(a[2]), "r"(a[3]), "r"(b[0]), "r"(b[1]));
}
__device__ __forceinline__ float gelu_tanh(float v) {
    const float c = 0.7978845608028654f;
    float t = tanhf(c * (v + 0.044715f * v * v * v));
    return 0.5f * v * (1.0f + t);
}

// ---------------- fused fp32->fp16 convert (w1, w2, x) ----------------
__global__ void cvt_all(const float4* __restrict__ x, const float4* __restrict__ w1,
                        const float4* __restrict__ w2) {
    const int NW = E * H * F / 4;
    const int NX = S * H / 4;
    int i = blockIdx.x * blockDim.x + threadIdx.x;
    if (i >= 2 * NW + NX) return;
    const float4* s;
    __half2* d;
    int j;
    if (i < NW) { s = w1; d = (__half2*)g_w1h; j = i; }
    else if (i < 2 * NW) { s = w2; d = (__half2*)g_w2h; j = i - NW; }
    else { s = x; d = (__half2*)g_xh; j = i - 2 * NW; }
    float4 v = s[j];
    d[2 * j]     = __floats2half2_rn(v.x, v.y);
    d[2 * j + 1] = __floats2half2_rn(v.z, v.w);
}

// ---------------- init: slots -> -1, out -> 0 ----------------
__global__ void init_kernel(float4* __restrict__ out) {
    int i = blockIdx.x * blockDim.x + threadIdx.x;
    if (i < E * CAP) g_slot_tok[i] = -1;
    if (i < S * H / 4) out[i] = make_float4(0.f, 0.f, 0.f, 0.f);
}

// ---------------- gating ----------------
__global__ void gate_kernel(const float* __restrict__ x, const float* __restrict__ wg) {
    int warp = (blockIdx.x * blockDim.x + threadIdx.x) >> 5;
    int lane = threadIdx.x & 31;
    if (warp >= S) return;
    const float* xr = x + (size_t)warp * H;
    float acc[E];
#pragma unroll
    for (int e = 0; e < E; e++) acc[e] = 0.0f;
    for (int k = lane; k < H; k += 32) {
        float xv = xr[k];
        const float* wr = wg + (size_t)k * E;
#pragma unroll
        for (int e = 0; e < E; e++) acc[e] += xv * wr[e];
    }
#pragma unroll
    for (int off = 16; off > 0; off >>= 1)
#pragma unroll
        for (int e = 0; e < E; e++)
            acc[e] += __shfl_down_sync(0xffffffffu, acc[e], off);
    if (lane == 0) {
        float mx = acc[0];
#pragma unroll
        for (int e = 1; e < E; e++) mx = fmaxf(mx, acc[e]);
        float g[E], sum = 0.0f;
#pragma unroll
        for (int e = 0; e < E; e++) { g[e] = expf(acc[e] - mx); sum += g[e]; }
        float inv = 1.0f / sum;
        int i1 = 0; float v1 = acc[0];
#pragma unroll
        for (int e = 1; e < E; e++) if (acc[e] > v1) { v1 = acc[e]; i1 = e; }
        int i2 = -1; float v2 = -3.4e38f;
#pragma unroll
        for (int e = 0; e < E; e++)
            if (e != i1 && acc[e] > v2) { v2 = acc[e]; i2 = e; }
#pragma unroll
        for (int e = 0; e < E; e++) g_gates[warp * E + e] = g[e] * inv;
        g_idx1[warp] = i1;
        g_idx2[warp] = i2;
    }
}

// ---------------- scan ----------------
__global__ void scan_kernel(float* __restrict__ out) {
    __shared__ int   sh_count1[E];
    __shared__ float sh_me[E];
    int warp = threadIdx.x >> 5;
    int lane = threadIdx.x & 31;
    unsigned lt_mask = (lane == 0) ? 0u : (0xffffffffu >> (32 - lane));
    {
        int e = warp, rank = 0;
        float mesum = 0.0f;
        for (int t0 = 0; t0 < S; t0 += 32) {
            int s = t0 + lane;
            int bit = (g_idx1[s] == e);
            unsigned m = __ballot_sync(0xffffffffu, bit);
            if (bit) {
                int r = rank + __popc(m & lt_mask);
                if (r < CAP) { g_c1[s] = r; g_slot_tok[e * CAP + r] = s; }
                else         { g_c1[s] = -1; }
            }
            rank += __popc(m);
            mesum += g_gates[s * E + e];
        }
#pragma unroll
        for (int off = 16; off > 0; off >>= 1)
            mesum += __shfl_down_sync(0xffffffffu, mesum, off);
        if (lane == 0) { sh_count1[e] = rank; sh_me[e] = mesum; }
    }
    __syncthreads();
    {
        int e = warp, base = sh_count1[e], rank = 0;
        for (int t0 = 0; t0 < S; t0 += 32) {
            int s = t0 + lane;
            int bit = (g_idx2[s] == e);
            unsigned m = __ballot_sync(0xffffffffu, bit);
            if (bit) {
                int r = base + rank + __popc(m & lt_mask);
                if (r < CAP) { g_c2[s] = r; g_slot_tok[e * CAP + r] = s; }
                else         { g_c2[s] = -1; }
            }
            rank += __popc(m);
        }
    }
    __syncthreads();
    for (int s = threadIdx.x; s < S; s += blockDim.x) {
        int i1 = g_idx1[s], i2 = g_idx2[s];
        int c1 = g_c1[s], c2 = g_c2[s];
        float g1 = (c1 >= 0) ? g_gates[s * E + i1] : 0.0f;
        float g2 = (c2 >= 0) ? g_gates[s * E + i2] : 0.0f;
        float denom = fmaxf(g1 + g2, 1.1920929e-7f);
        if (c1 >= 0) g_slot_w[i1 * CAP + c1] = g1 / denom;
        if (c2 >= 0) g_slot_w[i2 * CAP + c2] = g2 / denom;
    }
    if (threadIdx.x == 0) {
        float laux = 0.0f;
        const float invS = 1.0f / (float)S;
#pragma unroll
        for (int e = 0; e < E; e++)
            laux += (sh_me[e] * invS) * ((float)sh_count1[e] * invS);
        laux = laux * (float)E * 0.01f;
        out[(size_t)S * H] = laux;
#pragma unroll
        for (int e = 0; e < E; e++)
            out[(size_t)S * H + 1 + e] = (float)sh_count1[e];
    }
}

// ---------------- fp16 GEMM: cp.async 4-stage + ldmatrix + mma.m16n8k16 ----------------
// Block 128x128, BK=32, 8 warps (2M x 4N), warp tile 64x32.
// MODE 1: A = g_xh gathered, C = g_h (fp16, GELU).
// MODE 2: A = g_h dense, epilogue = fused combine (atomicAdd into out).
template <int MODE>
__global__ void __launch_bounds__(256, 2)
hgemm_async(const __half* __restrict__ Ah, const __half* __restrict__ Bh,
            float* __restrict__ out, int K, int N,
            size_t sAe, size_t sBe, size_t sCe) {
    extern __shared__ __align__(16) char smem[];
    const uint32_t sb = smem_u32(smem);

    int tid = threadIdx.x;
    int e = blockIdx.z;
    int m0 = blockIdx.y * BM;
    int n0 = blockIdx.x * BN;
    const __half* Be = Bh + e * sBe;

    // ---- loader mapping ----
    int arow = tid >> 1;
    int acs  = (tid & 1) * 2;
    const __half* a_src;
    int asz = 16;
    if (MODE == 1) {
        int tok = g_slot_tok[e * CAP + m0 + arow];
        a_src = (tok >= 0) ? (Ah + (size_t)tok * K) : Ah;
        asz = (tok >= 0) ? 16 : 0;
    } else {
        a_src = Ah + e * sAe + (size_t)(m0 + arow) * K;
    }
    uint32_t a_dst = sb + (uint32_t)arow * ASTB + (uint32_t)acs * 16;
    int brow = tid >> 3;
    int bcs  = (tid & 7) * 2;
    const __half* b_src = Be + (size_t)brow * N + n0 + bcs * 8;
    uint32_t b_dst = sb + A_BYTES + (uint32_t)brow * BSTB + (uint32_t)bcs * 16;

    // ---- fragment mapping ----
    int w = tid >> 5, lane = tid & 31;
    int wm = (w >> 2) * 64;
    int wn = (w & 3) * 32;
    uint32_t a_frag = sb + (uint32_t)(wm + (lane & 15)) * ASTB + (uint32_t)(lane >> 4) * 16;
    uint32_t b_frag = sb + A_BYTES + (uint32_t)((lane & 7) + ((lane >> 3) & 1) * 8) * BSTB
                         + (uint32_t)(wn + (lane >> 4) * 8) * 2;

    float acc[4][4][4];
#pragma unroll
    for (int i = 0; i < 4; i++)
#pragma unroll
        for (int j = 0; j < 4; j++)
#pragma unroll
            for (int r = 0; r < 4; r++) acc[i][j][r] = 0.0f;

    int ntiles = K / BKT;

    auto load_stage = [&](int buf, int k0) {
        uint32_t so = (uint32_t)buf * STAGE;
        const __half* as = a_src + k0 + acs * 8;
        if (MODE == 1) {
            cp16z(a_dst + so, as, asz);
            cp16z(a_dst + so + 16, as + 8, asz);
        } else {
            cp16(a_dst + so, as);
            cp16(a_dst + so + 16, as + 8);
        }
        const __half* bs = b_src + (size_t)k0 * N;
        cp16(b_dst + so, bs);
        cp16(b_dst + so + 16, bs + 8);
    };

    load_stage(0, 0); cp_commit();
    load_stage(1, BKT); cp_commit();
    load_stage(2, 2 * BKT); cp_commit();

    for (int it = 0; it < ntiles; it++) {
        if (it + 3 < ntiles) load_stage((it + 3) & 3, (it + 3) * BKT);
        cp_commit();
        cp_wait<3>();
        __syncthreads();

        uint32_t so = (uint32_t)(it & 3) * STAGE;
#pragma unroll
        for (int ks = 0; ks < 2; ks++) {
            uint32_t af[4][4];
#pragma unroll
            for (int i = 0; i < 4; i++)
                ldsm4(af[i], a_frag + so + (uint32_t)i * (16 * ASTB) + ks * 32);
            uint32_t bf[4][2];
#pragma unroll
            for (int jp = 0; jp < 2; jp++) {
                uint32_t r[4];
                ldsm4t(r, b_frag + so + (uint32_t)ks * (16 * BSTB) + jp * 32);
                bf[2 * jp][0] = r[0]; bf[2 * jp][1] = r[1];
                bf[2 * jp + 1][0] = r[2]; bf[2 * jp + 1][1] = r[3];
            }
#pragma unroll
            for (int i = 0; i < 4; i++)
#pragma unroll
                for (int j = 0; j < 4; j++)
                    mma16816(acc[i][j], af[i], bf[j]);
        }
        __syncthreads();
    }

    // ---- epilogue ----
    int gq = lane >> 2, tq = lane & 3;
    if (MODE == 1) {
        __half* Ch = g_h + e * sCe;
#pragma unroll
        for (int i = 0; i < 4; i++) {
            int row = m0 + wm + i * 16 + gq;
#pragma unroll
            for (int j = 0; j < 4; j++) {
                int col = n0 + wn + j * 8 + tq * 2;
                __half2 v0 = __floats2half2_rn(gelu_tanh(acc[i][j][0]), gelu_tanh(acc[i][j][1]));
                __half2 v1 = __floats2half2_rn(gelu_tanh(acc[i][j][2]), gelu_tanh(acc[i][j][3]));
                *reinterpret_cast<__half2*>(Ch + (size_t)row * N + col) = v0;
                *reinterpret_cast<__half2*>(Ch + (size_t)(row + 8) * N + col) = v1;
            }
        }
    } else {
        // fused combine: scatter-add weighted rows into out[token]
#pragma unroll
        for (int i = 0; i < 4; i++) {
            int r0 = m0 + wm + i * 16 + gq;           // slot row in [0, CAP)
            int s0 = e * CAP + r0;
            int t0 = g_slot_tok[s0], t1 = g_slot_tok[s0 + 8];
            float w0 = g_slot_w[s0], w1v = g_slot_w[s0 + 8];
            float* o0 = out + (size_t)t0 * H;
            float* o1 = out + (size_t)t1 * H;
#pragma unroll
            for (int j = 0; j < 4; j++) {
                int col = n0 + wn + j * 8 + tq * 2;
                if (t0 >= 0) {
                    atomicAdd(o0 + col,     w0 * acc[i][j][0]);
                    atomicAdd(o0 + col + 1, w0 * acc[i][j][1]);
                }
                if (t1 >= 0) {
                    atomicAdd(o1 + col,     w1v * acc[i][j][2]);
                    atomicAdd(o1 + col + 1, w1v * acc[i][j][3]);
                }
            }
        }
    }
}

// ---------------- launch ----------------
extern "C" void kernel_launch(void* const* d_in, const int* in_sizes, int n_in,
                              void* d_out, int out_size) {
    const float* x  = (const float*)d_in[0];
    const float* wg = (const float*)d_in[1];
    const float* w1 = (const float*)d_in[2];
    const float* w2 = (const float*)d_in[3];
    float* out = (float*)d_out;

    __half *xh, *w1h, *w2h, *hbuf;
    cudaGetSymbolAddress((void**)&xh,  g_xh);
    cudaGetSymbolAddress((void**)&w1h, g_w1h);
    cudaGetSymbolAddress((void**)&w2h, g_w2h);
    cudaGetSymbolAddress((void**)&hbuf, g_h);

    const int SMEM = NSTAGE * STAGE;   // 75776
    cudaFuncSetAttribute(hgemm_async<1>, cudaFuncAttributeMaxDynamicSharedMemorySize, SMEM);
    cudaFuncSetAttribute(hgemm_async<2>, cudaFuncAttributeMaxDynamicSharedMemorySize, SMEM);

    // 1) converts (w1, w2, x)
    {
        int total = 2 * (E * H * F / 4) + S * H / 4;
        cvt_all<<<(total + 255) / 256, 256>>>(
            (const float4*)x, (const float4*)w1, (const float4*)w2);
    }
    // 2) init slots + zero output
    init_kernel<<<(S * H / 4 + 255) / 256, 256>>>((float4*)out);
    // 3) gate, 4) scan
    gate_kernel<<<(S * 32 + 255) / 256, 256>>>(x, wg);
    scan_kernel<<<1, 256>>>(out);

    // 5) GEMM1: gathered xh [CAP,H] @ w1h[e][H,F] -> gelu -> g_h (fp16)
    hgemm_async<1><<<dim3(F / BN, CAP / BM, E), 256, SMEM>>>(
        xh, w1h, nullptr, H, F, 0, (size_t)H * F, (size_t)CAP * F);

    // 6) GEMM2: g_h [CAP,F] @ w2h[e][F,H] -> atomicAdd into out
    hgemm_async<2><<<dim3(H / BN, CAP / BM, E), 256, SMEM>>>(
        hbuf, w2h, out, F, H, (size_t)CAP * F, (size_t)F * H, 0);
}

// round 9
// speedup vs baseline: 4.7446x; 1.0868x over previous
#include <cuda_runtime.h>
#include <cuda_fp16.h>
#include <math.h>
#include <stdint.h>

#define S 2048
#define H 1024
#define F 4096
#define E 8
#define CAP 512
#define BM 128
#define BN 128
#define BKT 32

// smem strides (bytes)
#define ASTB 80            // 32 halfs + 8 pad
#define BSTB 272           // 128 halfs + 8 pad
#define A_BYTES (BM * ASTB)            // 10240
#define STAGE (A_BYTES + BKT * BSTB)   // 18944
#define NSTAGE 4

__device__ float  g_gates[S * E];
__device__ int    g_idx1[S];
__device__ int    g_idx2[S];
__device__ int    g_slot_tok[E * CAP];
__device__ float  g_slot_w[E * CAP];
__device__ __half g_xh[(size_t)S * H];          //  4 MB
__device__ __half g_w1h[(size_t)E * H * F];     // 67 MB
__device__ __half g_w2h[(size_t)E * F * H];     // 67 MB
__device__ __half g_h[(size_t)E * CAP * F];     // 33 MB

// ---------------- helpers ----------------
__device__ __forceinline__ uint32_t smem_u32(const void* p) {
    uint32_t a;
    asm("{ .reg .u64 t; cvta.to.shared.u64 t, %1; cvt.u32.u64 %0, t; }" : "=r"(a) : "l"(p));
    return a;
}
__device__ __forceinline__ void cp16(uint32_t dst, const void* src) {
    asm volatile("cp.async.cg.shared.global [%0], [%1], 16;" :: "r"(dst), "l"(src));
}
__device__ __forceinline__ void cp16z(uint32_t dst, const void* src, int srcsize) {
    asm volatile("cp.async.cg.shared.global [%0], [%1], 16, %2;"
                 :: "r"(dst), "l"(src), "r"(srcsize));
}
__device__ __forceinline__ void cp_commit() {
    asm volatile("cp.async.commit_group;" ::: "memory");
}
template <int N> __device__ __forceinline__ void cp_wait() {
    asm volatile("cp.async.wait_group %0;" :: "n"(N) : "memory");
}
__device__ __forceinline__ void ldsm4(uint32_t* r, uint32_t a) {
    asm volatile("ldmatrix.sync.aligned.m8n8.x4.shared.b16 {%0,%1,%2,%3}, [%4];"
                 : "=r"(r[0]), "=r"(r[1]), "=r"(r[2]), "=r"(r[3]) : "r"(a));
}
__device__ __forceinline__ void ldsm4t(uint32_t* r, uint32_t a) {
    asm volatile("ldmatrix.sync.aligned.m8n8.x4.trans.shared.b16 {%0,%1,%2,%3}, [%4];"
                 : "=r"(r[0]), "=r"(r[1]), "=r"(r[2]), "=r"(r[3]) : "r"(a));
}
__device__ __forceinline__ void mma16816(float* c, const uint32_t* a, const uint32_t* b) {
    asm volatile(
        "mma.sync.aligned.m16n8k16.row.col.f32.f16.f16.f32 "
        "{%0,%1,%2,%3}, {%4,%5,%6,%7}, {%8,%9}, {%0,%1,%2,%3};"
        : "+f"(c[0]), "+f"(c[1]), "+f"(c[2]), "+f"(c[3])
        : "r"(a[0]), "r"(a[1]), "r"(a[2]), "r"(a[3]), "r"(b[0]), "r"(b[1]));
}
__device__ __forceinline__ float gelu_tanh(float v) {
    const float c = 0.7978845608028654f;
    float t = tanhf(c * (v + 0.044715f * v * v * v));
    return 0.5f * v * (1.0f + t);
}

// ---------------- fp32 -> fp16 convert: w1 + w2 only ----------------
__global__ void cvt_w(const float4* __restrict__ w1, const float4* __restrict__ w2) {
    const int NW = E * H * F / 4;
    int i = blockIdx.x * blockDim.x + threadIdx.x;
    if (i >= 2 * NW) return;
    const float4* s;
    uint2* d;
    int j;
    if (i < NW) { s = w1; d = (uint2*)g_w1h; j = i; }
    else        { s = w2; d = (uint2*)g_w2h; j = i - NW; }
    float4 v = s[j];
    __half2 h0 = __floats2half2_rn(v.x, v.y);
    __half2 h1 = __floats2half2_rn(v.z, v.w);
    d[j] = make_uint2(*reinterpret_cast<uint32_t*>(&h0), *reinterpret_cast<uint32_t*>(&h1));
}

// ---------------- init: slots -> -1, out -> 0 ----------------
__global__ void init_kernel(float4* __restrict__ out) {
    int i = blockIdx.x * blockDim.x + threadIdx.x;
    if (i < E * CAP) g_slot_tok[i] = -1;
    if (i < S * H / 4) out[i] = make_float4(0.f, 0.f, 0.f, 0.f);
}

// ---------------- gating (also emits fp16 x) ----------------
__global__ void gate_kernel(const float* __restrict__ x, const float* __restrict__ wg) {
    int warp = (blockIdx.x * blockDim.x + threadIdx.x) >> 5;
    int lane = threadIdx.x & 31;
    if (warp >= S) return;
    const float* xr = x + (size_t)warp * H;
    __half* xhr = g_xh + (size_t)warp * H;
    float acc[E];
#pragma unroll
    for (int e = 0; e < E; e++) acc[e] = 0.0f;
    for (int k = lane; k < H; k += 32) {
        float xv = xr[k];
        xhr[k] = __float2half_rn(xv);
        const float* wr = wg + (size_t)k * E;
#pragma unroll
        for (int e = 0; e < E; e++) acc[e] += xv * wr[e];
    }
#pragma unroll
    for (int off = 16; off > 0; off >>= 1)
#pragma unroll
        for (int e = 0; e < E; e++)
            acc[e] += __shfl_down_sync(0xffffffffu, acc[e], off);
    if (lane == 0) {
        float mx = acc[0];
#pragma unroll
        for (int e = 1; e < E; e++) mx = fmaxf(mx, acc[e]);
        float g[E], sum = 0.0f;
#pragma unroll
        for (int e = 0; e < E; e++) { g[e] = expf(acc[e] - mx); sum += g[e]; }
        float inv = 1.0f / sum;
        int i1 = 0; float v1 = acc[0];
#pragma unroll
        for (int e = 1; e < E; e++) if (acc[e] > v1) { v1 = acc[e]; i1 = e; }
        int i2 = -1; float v2 = -3.4e38f;
#pragma unroll
        for (int e = 0; e < E; e++)
            if (e != i1 && acc[e] > v2) { v2 = acc[e]; i2 = e; }
#pragma unroll
        for (int e = 0; e < E; e++) g_gates[warp * E + e] = g[e] * inv;
        g_idx1[warp] = i1;
        g_idx2[warp] = i2;
    }
}

// ---------------- scan: smem-resident ballot scans ----------------
__global__ void scan_kernel(float* __restrict__ out) {
    __shared__ uint8_t sidx1[S];
    __shared__ uint8_t sidx2[S];
    __shared__ short   sc1[S];
    __shared__ short   sc2[S];
    __shared__ float   red[256 * E];      // 8 KB partial me sums
    __shared__ int     sh_count1[E];
    __shared__ float   sh_me[E];

    int tid = threadIdx.x;
    int warp = tid >> 5;
    int lane = tid & 31;
    unsigned lt_mask = (lane == 0) ? 0u : (0xffffffffu >> (32 - lane));

    // coalesced preload of expert indices into smem
    const int4* p1 = (const int4*)g_idx1;
    const int4* p2 = (const int4*)g_idx2;
    for (int i = tid; i < S / 4; i += 256) {
        int4 v = p1[i];
        sidx1[4 * i] = (uint8_t)v.x; sidx1[4 * i + 1] = (uint8_t)v.y;
        sidx1[4 * i + 2] = (uint8_t)v.z; sidx1[4 * i + 3] = (uint8_t)v.w;
        int4 u = p2[i];
        sidx2[4 * i] = (uint8_t)u.x; sidx2[4 * i + 1] = (uint8_t)u.y;
        sidx2[4 * i + 2] = (uint8_t)u.z; sidx2[4 * i + 3] = (uint8_t)u.w;
    }

    // parallel me-sum: each thread accumulates 8 rows, tree-reduce per column
    {
        float acc[E];
#pragma unroll
        for (int e = 0; e < E; e++) acc[e] = 0.0f;
        for (int s = tid; s < S; s += 256) {
            const float4* g = (const float4*)(g_gates + (size_t)s * E);
            float4 a = g[0], b = g[1];
            acc[0] += a.x; acc[1] += a.y; acc[2] += a.z; acc[3] += a.w;
            acc[4] += b.x; acc[5] += b.y; acc[6] += b.z; acc[7] += b.w;
        }
#pragma unroll
        for (int e = 0; e < E; e++) red[e * 256 + tid] = acc[e];
    }
    __syncthreads();
    {
        // warp e reduces its 256 partials
        float v = 0.0f;
        for (int i = lane; i < 256; i += 32) v += red[warp * 256 + i];
#pragma unroll
        for (int off = 16; off > 0; off >>= 1) v += __shfl_down_sync(0xffffffffu, v, off);
        if (lane == 0) sh_me[warp] = v;
    }

    // Phase A: first-choice ranks from smem
    {
        int e = warp, rank = 0;
        for (int t0 = 0; t0 < S; t0 += 32) {
            int s = t0 + lane;
            int bit = (sidx1[s] == e);
            unsigned m = __ballot_sync(0xffffffffu, bit);
            if (bit) {
                int r = rank + __popc(m & lt_mask);
                if (r < CAP) { sc1[s] = (short)r; g_slot_tok[e * CAP + r] = s; }
                else         { sc1[s] = -1; }
            }
            rank += __popc(m);
        }
        if (lane == 0) sh_count1[e] = rank;
    }
    __syncthreads();

    // Phase B: second-choice ranks, offset by count1
    {
        int e = warp, base = sh_count1[e], rank = 0;
        for (int t0 = 0; t0 < S; t0 += 32) {
            int s = t0 + lane;
            int bit = (sidx2[s] == e);
            unsigned m = __ballot_sync(0xffffffffu, bit);
            if (bit) {
                int r = base + rank + __popc(m & lt_mask);
                if (r < CAP) { sc2[s] = (short)r; g_slot_tok[e * CAP + r] = s; }
                else         { sc2[s] = -1; }
            }
            rank += __popc(m);
        }
    }
    __syncthreads();

    // Phase C: normalized combine weights to slot table
    for (int s = tid; s < S; s += 256) {
        int i1 = sidx1[s], i2 = sidx2[s];
        int c1 = sc1[s], c2 = sc2[s];
        float g1 = (c1 >= 0) ? g_gates[(size_t)s * E + i1] : 0.0f;
        float g2 = (c2 >= 0) ? g_gates[(size_t)s * E + i2] : 0.0f;
        float denom = fmaxf(g1 + g2, 1.1920929e-7f);
        if (c1 >= 0) g_slot_w[i1 * CAP + c1] = g1 / denom;
        if (c2 >= 0) g_slot_w[i2 * CAP + c2] = g2 / denom;
    }

    // aux loss + expert counts
    if (tid == 0) {
        float laux = 0.0f;
        const float invS = 1.0f / (float)S;
#pragma unroll
        for (int e = 0; e < E; e++)
            laux += (sh_me[e] * invS) * ((float)sh_count1[e] * invS);
        laux = laux * (float)E * 0.01f;
        out[(size_t)S * H] = laux;
#pragma unroll
        for (int e = 0; e < E; e++)
            out[(size_t)S * H + 1 + e] = (float)sh_count1[e];
    }
}

// ---------------- fp16 GEMM: cp.async 4-stage + ldmatrix + mma.m16n8k16 ----------------
// Block 128x128, BK=32, 8 warps (2M x 4N), warp tile 64x32.
// MODE 1: A = g_xh gathered, C = g_h (fp16, GELU).
// MODE 2: A = g_h dense, epilogue = fused combine (atomicAdd into out).
template <int MODE>
__global__ void __launch_bounds__(256, 2)
hgemm_async(const __half* __restrict__ Ah, const __half* __restrict__ Bh,
            float* __restrict__ out, int K, int N,
            size_t sAe, size_t sBe, size_t sCe) {
    extern __shared__ __align__(16) char smem[];
    const uint32_t sb = smem_u32(smem);

    int tid = threadIdx.x;
    int e = blockIdx.z;
    int m0 = blockIdx.y * BM;
    int n0 = blockIdx.x * BN;
    const __half* Be = Bh + e * sBe;

    // ---- loader mapping ----
    int arow = tid >> 1;
    int acs  = (tid & 1) * 2;
    const __half* a_src;
    int asz = 16;
    if (MODE == 1) {
        int tok = g_slot_tok[e * CAP + m0 + arow];
        a_src = (tok >= 0) ? (Ah + (size_t)tok * K) : Ah;
        asz = (tok >= 0) ? 16 : 0;
    } else {
        a_src = Ah + e * sAe + (size_t)(m0 + arow) * K;
    }
    uint32_t a_dst = sb + (uint32_t)arow * ASTB + (uint32_t)acs * 16;
    int brow = tid >> 3;
    int bcs  = (tid & 7) * 2;
    const __half* b_src = Be + (size_t)brow * N + n0 + bcs * 8;
    uint32_t b_dst = sb + A_BYTES + (uint32_t)brow * BSTB + (uint32_t)bcs * 16;

    // ---- fragment mapping ----
    int w = tid >> 5, lane = tid & 31;
    int wm = (w >> 2) * 64;
    int wn = (w & 3) * 32;
    uint32_t a_frag = sb + (uint32_t)(wm + (lane & 15)) * ASTB + (uint32_t)(lane >> 4) * 16;
    uint32_t b_frag = sb + A_BYTES + (uint32_t)((lane & 7) + ((lane >> 3) & 1) * 8) * BSTB
                         + (uint32_t)(wn + (lane >> 4) * 8) * 2;

    float acc[4][4][4];
#pragma unroll
    for (int i = 0; i < 4; i++)
#pragma unroll
        for (int j = 0; j < 4; j++)
#pragma unroll
            for (int r = 0; r < 4; r++) acc[i][j][r] = 0.0f;

    int ntiles = K / BKT;

    auto load_stage = [&](int buf, int k0) {
        uint32_t so = (uint32_t)buf * STAGE;
        const __half* as = a_src + k0 + acs * 8;
        if (MODE == 1) {
            cp16z(a_dst + so, as, asz);
            cp16z(a_dst + so + 16, as + 8, asz);
        } else {
            cp16(a_dst + so, as);
            cp16(a_dst + so + 16, as + 8);
        }
        const __half* bs = b_src + (size_t)k0 * N;
        cp16(b_dst + so, bs);
        cp16(b_dst + so + 16, bs + 8);
    };

    load_stage(0, 0); cp_commit();
    load_stage(1, BKT); cp_commit();
    load_stage(2, 2 * BKT); cp_commit();

    for (int it = 0; it < ntiles; it++) {
        if (it + 3 < ntiles) load_stage((it + 3) & 3, (it + 3) * BKT);
        cp_commit();
        cp_wait<3>();
        __syncthreads();

        uint32_t so = (uint32_t)(it & 3) * STAGE;
#pragma unroll
        for (int ks = 0; ks < 2; ks++) {
            uint32_t af[4][4];
#pragma unroll
            for (int i = 0; i < 4; i++)
                ldsm4(af[i], a_frag + so + (uint32_t)i * (16 * ASTB) + ks * 32);
            uint32_t bf[4][2];
#pragma unroll
            for (int jp = 0; jp < 2; jp++) {
                uint32_t r[4];
                ldsm4t(r, b_frag + so + (uint32_t)ks * (16 * BSTB) + jp * 32);
                bf[2 * jp][0] = r[0]; bf[2 * jp][1] = r[1];
                bf[2 * jp + 1][0] = r[2]; bf[2 * jp + 1][1] = r[3];
            }
#pragma unroll
            for (int i = 0; i < 4; i++)
#pragma unroll
                for (int j = 0; j < 4; j++)
                    mma16816(acc[i][j], af[i], bf[j]);
        }
        __syncthreads();
    }

    // ---- epilogue ----
    int gq = lane >> 2, tq = lane & 3;
    if (MODE == 1) {
        __half* Ch = g_h + e * sCe;
#pragma unroll
        for (int i = 0; i < 4; i++) {
            int row = m0 + wm + i * 16 + gq;
#pragma unroll
            for (int j = 0; j < 4; j++) {
                int col = n0 + wn + j * 8 + tq * 2;
                __half2 v0 = __floats2half2_rn(gelu_tanh(acc[i][j][0]), gelu_tanh(acc[i][j][1]));
                __half2 v1 = __floats2half2_rn(gelu_tanh(acc[i][j][2]), gelu_tanh(acc[i][j][3]));
                *reinterpret_cast<__half2*>(Ch + (size_t)row * N + col) = v0;
                *reinterpret_cast<__half2*>(Ch + (size_t)(row + 8) * N + col) = v1;
            }
        }
    } else {
        // fused combine: scatter-add weighted rows into out[token]
#pragma unroll
        for (int i = 0; i < 4; i++) {
            int r0 = m0 + wm + i * 16 + gq;           // slot row in [0, CAP)
            int s0 = e * CAP + r0;
            int t0 = g_slot_tok[s0], t1 = g_slot_tok[s0 + 8];
            float w0 = g_slot_w[s0], w1v = g_slot_w[s0 + 8];
            float* o0 = out + (size_t)t0 * H;
            float* o1 = out + (size_t)t1 * H;
#pragma unroll
            for (int j = 0; j < 4; j++) {
                int col = n0 + wn + j * 8 + tq * 2;
                if (t0 >= 0) {
                    atomicAdd(o0 + col,     w0 * acc[i][j][0]);
                    atomicAdd(o0 + col + 1, w0 * acc[i][j][1]);
                }
                if (t1 >= 0) {
                    atomicAdd(o1 + col,     w1v * acc[i][j][2]);
                    atomicAdd(o1 + col + 1, w1v * acc[i][j][3]);
                }
            }
        }
    }
}

// ---------------- launch ----------------
extern "C" void kernel_launch(void* const* d_in, const int* in_sizes, int n_in,
                              void* d_out, int out_size) {
    const float* x  = (const float*)d_in[0];
    const float* wg = (const float*)d_in[1];
    const float* w1 = (const float*)d_in[2];
    const float* w2 = (const float*)d_in[3];
    float* out = (float*)d_out;

    __half *xh, *w1h, *w2h, *hbuf;
    cudaGetSymbolAddress((void**)&xh,  g_xh);
    cudaGetSymbolAddress((void**)&w1h, g_w1h);
    cudaGetSymbolAddress((void**)&w2h, g_w2h);
    cudaGetSymbolAddress((void**)&hbuf, g_h);

    const int SMEM = NSTAGE * STAGE;   // 75776
    cudaFuncSetAttribute(hgemm_async<1>, cudaFuncAttributeMaxDynamicSharedMemorySize, SMEM);
    cudaFuncSetAttribute(hgemm_async<2>, cudaFuncAttributeMaxDynamicSharedMemorySize, SMEM);

    // 1) weight converts (w1, w2)
    {
        int total = 2 * (E * H * F / 4);
        cvt_w<<<(total + 255) / 256, 256>>>((const float4*)w1, (const float4*)w2);
    }
    // 2) init slots + zero output
    init_kernel<<<(S * H / 4 + 255) / 256, 256>>>((float4*)out);
    // 3) gate (also writes g_xh), 4) scan (smem-resident)
    gate_kernel<<<(S * 32 + 255) / 256, 256>>>(x, wg);
    scan_kernel<<<1, 256>>>(out);

    // 5) GEMM1: gathered xh [CAP,H] @ w1h[e][H,F] -> gelu -> g_h (fp16)
    hgemm_async<1><<<dim3(F / BN, CAP / BM, E), 256, SMEM>>>(
        xh, w1h, nullptr, H, F, 0, (size_t)H * F, (size_t)CAP * F);

    // 6) GEMM2: g_h [CAP,F] @ w2h[e][F,H] -> atomicAdd into out
    hgemm_async<2><<<dim3(H / BN, CAP / BM, E), 256, SMEM>>>(
        hbuf, w2h, out, F, H, (size_t)CAP * F, (size_t)F * H, 0);
}

// round 11
// speedup vs baseline: 4.9615x; 1.0457x over previous
#include <cuda_runtime.h>
#include <cuda_fp16.h>
#include <math.h>
#include <stdint.h>

#define S 2048
#define H 1024
#define F 4096
#define E 8
#define CAP 512
#define BM 128
#define BN 128
#define BKT 32

// smem strides (bytes)
#define ASTB 80            // 32 halfs + 8 pad
#define BSTB 272           // 128 halfs + 8 pad
#define A_BYTES (BM * ASTB)            // 10240
#define STAGE (A_BYTES + BKT * BSTB)   // 18944
#define NSTAGE 4

__device__ float  g_gates[S * E];
__device__ int    g_idx1[S];
__device__ int    g_idx2[S];
__device__ int    g_slot_tok[E * CAP];
__device__ float  g_slot_w[E * CAP];
__device__ __half g_xh[(size_t)S * H];
__device__ __half g_w1h[(size_t)E * H * F];
__device__ __half g_w2h[(size_t)E * F * H];
__device__ __half g_h[(size_t)E * CAP * F];

// ---------------- helpers ----------------
__device__ __forceinline__ uint32_t smem_u32(const void* p) {
    uint32_t a;
    asm("{ .reg .u64 t; cvta.to.shared.u64 t, %1; cvt.u32.u64 %0, t; }" : "=r"(a) : "l"(p));
    return a;
}
__device__ __forceinline__ void cp16(uint32_t dst, const void* src) {
    asm volatile("cp.async.cg.shared.global [%0], [%1], 16;" :: "r"(dst), "l"(src));
}
__device__ __forceinline__ void cp16z(uint32_t dst, const void* src, int srcsize) {
    asm volatile("cp.async.cg.shared.global [%0], [%1], 16, %2;"
                 :: "r"(dst), "l"(src), "r"(srcsize));
}
__device__ __forceinline__ void cp_commit() {
    asm volatile("cp.async.commit_group;" ::: "memory");
}
template <int N> __device__ __forceinline__ void cp_wait() {
    asm volatile("cp.async.wait_group %0;" :: "n"(N) : "memory");
}
__device__ __forceinline__ void ldsm4(uint32_t* r, uint32_t a) {
    asm volatile("ldmatrix.sync.aligned.m8n8.x4.shared.b16 {%0,%1,%2,%3}, [%4];"
                 : "=r"(r[0]), "=r"(r[1]), "=r"(r[2]), "=r"(r[3]) : "r"(a));
}
__device__ __forceinline__ void ldsm4t(uint32_t* r, uint32_t a) {
    asm volatile("ldmatrix.sync.aligned.m8n8.x4.trans.shared.b16 {%0,%1,%2,%3}, [%4];"
                 : "=r"(r[0]), "=r"(r[1]), "=r"(r[2]), "=r"(r[3]) : "r"(a));
}
__device__ __forceinline__ void mma16816(float* c, const uint32_t* a, const uint32_t* b) {
    asm volatile(
        "mma.sync.aligned.m16n8k16.row.col.f32.f16.f16.f32 "
        "{%0,%1,%2,%3}, {%4,%5,%6,%7}, {%8,%9}, {%0,%1,%2,%3};"
        : "+f"(c[0]), "+f"(c[1]), "+f"(c[2]), "+f"(c[3])
        : "r"(a[0]), "r"(a[1]), "r"(a[2]), "r"(a[3]), "r"(b[0]), "r"(b[1]));
}
__device__ __forceinline__ float gelu_tanh(float v) {
    const float c = 0.7978845608028654f;
    float t = tanhf(c * (v + 0.044715f * v * v * v));
    return 0.5f * v * (1.0f + t);
}

// ---------------- fp32 -> fp16 convert (one tensor) ----------------
__global__ void cvt_one(const float4* __restrict__ src, uint2* __restrict__ dst, int n4) {
    int i = blockIdx.x * blockDim.x + threadIdx.x;
    if (i >= n4) return;
    float4 v = src[i];
    __half2 h0 = __floats2half2_rn(v.x, v.y);
    __half2 h1 = __floats2half2_rn(v.z, v.w);
    dst[i] = make_uint2(*reinterpret_cast<uint32_t*>(&h0), *reinterpret_cast<uint32_t*>(&h1));
}

// ---------------- init: slots -> -1, out -> 0 ----------------
__global__ void init_kernel(float4* __restrict__ out) {
    int i = blockIdx.x * blockDim.x + threadIdx.x;
    if (i < E * CAP) g_slot_tok[i] = -1;
    if (i < S * H / 4) out[i] = make_float4(0.f, 0.f, 0.f, 0.f);
}

// ---------------- gating (also emits fp16 x) ----------------
__global__ void gate_kernel(const float* __restrict__ x, const float* __restrict__ wg) {
    int warp = (blockIdx.x * blockDim.x + threadIdx.x) >> 5;
    int lane = threadIdx.x & 31;
    if (warp >= S) return;
    const float* xr = x + (size_t)warp * H;
    __half* xhr = g_xh + (size_t)warp * H;
    float acc[E];
#pragma unroll
    for (int e = 0; e < E; e++) acc[e] = 0.0f;
    for (int k = lane; k < H; k += 32) {
        float xv = xr[k];
        xhr[k] = __float2half_rn(xv);
        const float* wr = wg + (size_t)k * E;
#pragma unroll
        for (int e = 0; e < E; e++) acc[e] += xv * wr[e];
    }
#pragma unroll
    for (int off = 16; off > 0; off >>= 1)
#pragma unroll
        for (int e = 0; e < E; e++)
            acc[e] += __shfl_down_sync(0xffffffffu, acc[e], off);
    if (lane == 0) {
        float mx = acc[0];
#pragma unroll
        for (int e = 1; e < E; e++) mx = fmaxf(mx, acc[e]);
        float g[E], sum = 0.0f;
#pragma unroll
        for (int e = 0; e < E; e++) { g[e] = expf(acc[e] - mx); sum += g[e]; }
        float inv = 1.0f / sum;
        int i1 = 0; float v1 = acc[0];
#pragma unroll
        for (int e = 1; e < E; e++) if (acc[e] > v1) { v1 = acc[e]; i1 = e; }
        int i2 = -1; float v2 = -3.4e38f;
#pragma unroll
        for (int e = 0; e < E; e++)
            if (e != i1 && acc[e] > v2) { v2 = acc[e]; i2 = e; }
#pragma unroll
        for (int e = 0; e < E; e++) g_gates[warp * E + e] = g[e] * inv;
        g_idx1[warp] = i1;
        g_idx2[warp] = i2;
    }
}

// ---------------- scan: smem-resident ballot scans ----------------
__global__ void scan_kernel(float* __restrict__ out) {
    __shared__ uint8_t sidx1[S];
    __shared__ uint8_t sidx2[S];
    __shared__ short   sc1[S];
    __shared__ short   sc2[S];
    __shared__ float   red[256 * E];
    __shared__ int     sh_count1[E];
    __shared__ float   sh_me[E];

    int tid = threadIdx.x;
    int warp = tid >> 5;
    int lane = tid & 31;
    unsigned lt_mask = (lane == 0) ? 0u : (0xffffffffu >> (32 - lane));

    const int4* p1 = (const int4*)g_idx1;
    const int4* p2 = (const int4*)g_idx2;
    for (int i = tid; i < S / 4; i += 256) {
        int4 v = p1[i];
        sidx1[4 * i] = (uint8_t)v.x; sidx1[4 * i + 1] = (uint8_t)v.y;
        sidx1[4 * i + 2] = (uint8_t)v.z; sidx1[4 * i + 3] = (uint8_t)v.w;
        int4 u = p2[i];
        sidx2[4 * i] = (uint8_t)u.x; sidx2[4 * i + 1] = (uint8_t)u.y;
        sidx2[4 * i + 2] = (uint8_t)u.z; sidx2[4 * i + 3] = (uint8_t)u.w;
    }
    {
        float acc[E];
#pragma unroll
        for (int e = 0; e < E; e++) acc[e] = 0.0f;
        for (int s = tid; s < S; s += 256) {
            const float4* g = (const float4*)(g_gates + (size_t)s * E);
            float4 a = g[0], b = g[1];
            acc[0] += a.x; acc[1] += a.y; acc[2] += a.z; acc[3] += a.w;
            acc[4] += b.x; acc[5] += b.y; acc[6] += b.z; acc[7] += b.w;
        }
#pragma unroll
        for (int e = 0; e < E; e++) red[e * 256 + tid] = acc[e];
    }
    __syncthreads();
    {
        float v = 0.0f;
        for (int i = lane; i < 256; i += 32) v += red[warp * 256 + i];
#pragma unroll
        for (int off = 16; off > 0; off >>= 1) v += __shfl_down_sync(0xffffffffu, v, off);
        if (lane == 0) sh_me[warp] = v;
    }
    {
        int e = warp, rank = 0;
        for (int t0 = 0; t0 < S; t0 += 32) {
            int s = t0 + lane;
            int bit = (sidx1[s] == e);
            unsigned m = __ballot_sync(0xffffffffu, bit);
            if (bit) {
                int r = rank + __popc(m & lt_mask);
                if (r < CAP) { sc1[s] = (short)r; g_slot_tok[e * CAP + r] = s; }
                else         { sc1[s] = -1; }
            }
            rank += __popc(m);
        }
        if (lane == 0) sh_count1[e] = rank;
    }
    __syncthreads();
    {
        int e = warp, base = sh_count1[e], rank = 0;
        for (int t0 = 0; t0 < S; t0 += 32) {
            int s = t0 + lane;
            int bit = (sidx2[s] == e);
            unsigned m = __ballot_sync(0xffffffffu, bit);
            if (bit) {
                int r = base + rank + __popc(m & lt_mask);
                if (r < CAP) { sc2[s] = (short)r; g_slot_tok[e * CAP + r] = s; }
                else         { sc2[s] = -1; }
            }
            rank += __popc(m);
        }
    }
    __syncthreads();
    for (int s = tid; s < S; s += 256) {
        int i1 = sidx1[s], i2 = sidx2[s];
        int c1 = sc1[s], c2 = sc2[s];
        float g1 = (c1 >= 0) ? g_gates[(size_t)s * E + i1] : 0.0f;
        float g2 = (c2 >= 0) ? g_gates[(size_t)s * E + i2] : 0.0f;
        float denom = fmaxf(g1 + g2, 1.1920929e-7f);
        if (c1 >= 0) g_slot_w[i1 * CAP + c1] = g1 / denom;
        if (c2 >= 0) g_slot_w[i2 * CAP + c2] = g2 / denom;
    }
    if (tid == 0) {
        float laux = 0.0f;
        const float invS = 1.0f / (float)S;
#pragma unroll
        for (int e = 0; e < E; e++)
            laux += (sh_me[e] * invS) * ((float)sh_count1[e] * invS);
        laux = laux * (float)E * 0.01f;
        out[(size_t)S * H] = laux;
#pragma unroll
        for (int e = 0; e < E; e++)
            out[(size_t)S * H + 1 + e] = (float)sh_count1[e];
    }
}

// ---------------- fp16 GEMM: cp.async 4-stage, single sync per k-iter ----------------
// Block 128x128, BK=32, 8 warps (2M x 4N), warp tile 64x32.
// MODE 1: A = g_xh gathered, C = g_h (fp16, GELU).
// MODE 2: A = g_h dense, epilogue = fused combine (atomicAdd into out).
template <int MODE>
__global__ void __launch_bounds__(256, 2)
hgemm_async(const __half* __restrict__ Ah, const __half* __restrict__ Bh,
            float* __restrict__ out, int K, int N,
            size_t sAe, size_t sBe, size_t sCe) {
    extern __shared__ __align__(16) char smem[];
    const uint32_t sb = smem_u32(smem);

    int tid = threadIdx.x;
    int e = blockIdx.z;
    int m0 = blockIdx.y * BM;
    int n0 = blockIdx.x * BN;
    const __half* Be = Bh + e * sBe;

    // ---- loader mapping ----
    int arow = tid >> 1;
    int acs  = (tid & 1) * 2;
    const __half* a_src;
    int asz = 16;
    if (MODE == 1) {
        int tok = g_slot_tok[e * CAP + m0 + arow];
        a_src = (tok >= 0) ? (Ah + (size_t)tok * K) : Ah;
        asz = (tok >= 0) ? 16 : 0;
    } else {
        a_src = Ah + e * sAe + (size_t)(m0 + arow) * K;
    }
    uint32_t a_dst = sb + (uint32_t)arow * ASTB + (uint32_t)acs * 16;
    int brow = tid >> 3;
    int bcs  = (tid & 7) * 2;
    const __half* b_src = Be + (size_t)brow * N + n0 + bcs * 8;
    uint32_t b_dst = sb + A_BYTES + (uint32_t)brow * BSTB + (uint32_t)bcs * 16;

    // ---- fragment mapping ----
    int w = tid >> 5, lane = tid & 31;
    int wm = (w >> 2) * 64;
    int wn = (w & 3) * 32;
    uint32_t a_frag = sb + (uint32_t)(wm + (lane & 15)) * ASTB + (uint32_t)(lane >> 4) * 16;
    uint32_t b_frag = sb + A_BYTES + (uint32_t)((lane & 7) + ((lane >> 3) & 1) * 8) * BSTB
                         + (uint32_t)(wn + (lane >> 4) * 8) * 2;

    float acc[4][4][4];
#pragma unroll
    for (int i = 0; i < 4; i++)
#pragma unroll
        for (int j = 0; j < 4; j++)
#pragma unroll
            for (int r = 0; r < 4; r++) acc[i][j][r] = 0.0f;

    int ntiles = K / BKT;

    auto load_stage = [&](int buf, int k0) {
        uint32_t so = (uint32_t)buf * STAGE;
        const __half* as = a_src + k0 + acs * 8;
        if (MODE == 1) {
            cp16z(a_dst + so, as, asz);
            cp16z(a_dst + so + 16, as + 8, asz);
        } else {
            cp16(a_dst + so, as);
            cp16(a_dst + so + 16, as + 8);
        }
        const __half* bs = b_src + (size_t)k0 * N;
        cp16(b_dst + so, bs);
        cp16(b_dst + so + 16, bs + 8);
    };

    load_stage(0, 0); cp_commit();
    load_stage(1, BKT); cp_commit();
    load_stage(2, 2 * BKT); cp_commit();

    for (int it = 0; it < ntiles; it++) {
        cp_wait<2>();
        __syncthreads();

        uint32_t so = (uint32_t)(it & 3) * STAGE;
#pragma unroll
        for (int ks = 0; ks < 2; ks++) {
            uint32_t af[4][4];
#pragma unroll
            for (int i = 0; i < 4; i++)
                ldsm4(af[i], a_frag + so + (uint32_t)i * (16 * ASTB) + ks * 32);
            uint32_t bf[4][2];
#pragma unroll
            for (int jp = 0; jp < 2; jp++) {
                uint32_t r[4];
                ldsm4t(r, b_frag + so + (uint32_t)ks * (16 * BSTB) + jp * 32);
                bf[2 * jp][0] = r[0]; bf[2 * jp][1] = r[1];
                bf[2 * jp + 1][0] = r[2]; bf[2 * jp + 1][1] = r[3];
            }
#pragma unroll
            for (int i = 0; i < 4; i++)
#pragma unroll
                for (int j = 0; j < 4; j++)
                    mma16816(acc[i][j], af[i], bf[j]);
        }

        // prefetch stage it+3 into buffer (it+3)&3 (disjoint from it&3;
        // all warps are inside iteration `it` thanks to the barrier above)
        if (it + 3 < ntiles) load_stage((it + 3) & 3, (it + 3) * BKT);
        cp_commit();
    }

    // ---- epilogue ----
    int gq = lane >> 2, tq = lane & 3;
    if (MODE == 1) {
        __half* Ch = g_h + e * sCe;
#pragma unroll
        for (int i = 0; i < 4; i++) {
            int row = m0 + wm + i * 16 + gq;
#pragma unroll
            for (int j = 0; j < 4; j++) {
                int col = n0 + wn + j * 8 + tq * 2;
                __half2 v0 = __floats2half2_rn(gelu_tanh(acc[i][j][0]), gelu_tanh(acc[i][j][1]));
                __half2 v1 = __floats2half2_rn(gelu_tanh(acc[i][j][2]), gelu_tanh(acc[i][j][3]));
                *reinterpret_cast<__half2*>(Ch + (size_t)row * N + col) = v0;
                *reinterpret_cast<__half2*>(Ch + (size_t)(row + 8) * N + col) = v1;
            }
        }
    } else {
#pragma unroll
        for (int i = 0; i < 4; i++) {
            int r0 = m0 + wm + i * 16 + gq;
            int s0 = e * CAP + r0;
            int t0 = g_slot_tok[s0], t1 = g_slot_tok[s0 + 8];
            float w0 = g_slot_w[s0], w1v = g_slot_w[s0 + 8];
            float* o0 = out + (size_t)t0 * H;
            float* o1 = out + (size_t)t1 * H;
#pragma unroll
            for (int j = 0; j < 4; j++) {
                int col = n0 + wn + j * 8 + tq * 2;
                if (t0 >= 0) {
                    atomicAdd(o0 + col,     w0 * acc[i][j][0]);
                    atomicAdd(o0 + col + 1, w0 * acc[i][j][1]);
                }
                if (t1 >= 0) {
                    atomicAdd(o1 + col,     w1v * acc[i][j][2]);
                    atomicAdd(o1 + col + 1, w1v * acc[i][j][3]);
                }
            }
        }
    }
}

// ---------------- launch ----------------
extern "C" void kernel_launch(void* const* d_in, const int* in_sizes, int n_in,
                              void* d_out, int out_size) {
    const float* x  = (const float*)d_in[0];
    const float* wg = (const float*)d_in[1];
    const float* w1 = (const float*)d_in[2];
    const float* w2 = (const float*)d_in[3];
    float* out = (float*)d_out;

    __half *xh, *w1h, *w2h, *hbuf;
    cudaGetSymbolAddress((void**)&xh,  g_xh);
    cudaGetSymbolAddress((void**)&w1h, g_w1h);
    cudaGetSymbolAddress((void**)&w2h, g_w2h);
    cudaGetSymbolAddress((void**)&hbuf, g_h);

    const int SMEM = NSTAGE * STAGE;   // 75776
    cudaFuncSetAttribute(hgemm_async<1>, cudaFuncAttributeMaxDynamicSharedMemorySize, SMEM);
    cudaFuncSetAttribute(hgemm_async<2>, cudaFuncAttributeMaxDynamicSharedMemorySize, SMEM);

    // side streams + events for graph fork/join (host resources, created once;
    // per-call captured WORK is identical every call)
    static cudaStream_t sA = nullptr, sB = nullptr;
    static cudaEvent_t eFork = nullptr, eW1 = nullptr, eW2 = nullptr;
    if (sA == nullptr) {
        cudaStreamCreateWithFlags(&sA, cudaStreamNonBlocking);
        cudaStreamCreateWithFlags(&sB, cudaStreamNonBlocking);
        cudaEventCreateWithFlags(&eFork, cudaEventDisableTiming);
        cudaEventCreateWithFlags(&eW1, cudaEventDisableTiming);
        cudaEventCreateWithFlags(&eW2, cudaEventDisableTiming);
    }

    const int NW4 = E * H * F / 4;   // float4 count per weight tensor

    // fork: weight converts run concurrently with gating chain
    cudaEventRecord(eFork, 0);
    cudaStreamWaitEvent(sA, eFork, 0);
    cudaStreamWaitEvent(sB, eFork, 0);
    cvt_one<<<(NW4 + 255) / 256, 256, 0, sA>>>((const float4*)w1, (uint2*)w1h, NW4);
    cvt_one<<<(NW4 + 255) / 256, 256, 0, sB>>>((const float4*)w2, (uint2*)w2h, NW4);
    cudaEventRecord(eW1, sA);
    cudaEventRecord(eW2, sB);

    // main chain: init, gate (writes g_xh), scan
    init_kernel<<<(S * H / 4 + 255) / 256, 256>>>((float4*)out);
    gate_kernel<<<(S * 32 + 255) / 256, 256>>>(x, wg);
    scan_kernel<<<1, 256>>>(out);

    // GEMM1 needs w1h + g_xh + slot tables
    cudaStreamWaitEvent(0, eW1, 0);
    hgemm_async<1><<<dim3(F / BN, CAP / BM, E), 256, SMEM>>>(
        xh, w1h, nullptr, H, F, 0, (size_t)H * F, (size_t)CAP * F);

    // GEMM2 needs g_h + w2h (join sB)
    cudaStreamWaitEvent(0, eW2, 0);
    hgemm_async<2><<<dim3(H / BN, CAP / BM, E), 256, SMEM>>>(
        hbuf, w2h, out, F, H, (size_t)CAP * F, (size_t)F * H, 0);
}